// round 1
// baseline (speedup 1.0000x reference)
#include <cuda_runtime.h>
#include <cstdint>

#define NN 100000
#define EE 1000000
#define HH 128
#define FN 64
#define FE 32
#define CN 12
#define CE 4

// Scratch (device globals — no cudaMalloc allowed)
__device__ float g_h  [(size_t)NN * HH];
__device__ float g_xw [(size_t)NN * HH];
__device__ float g_acc[(size_t)NN * HH];
__device__ float g_dinv[NN];
__device__ int   g_deg [NN];

// ---------------------------------------------------------------------------
// Degree / normalization
// ---------------------------------------------------------------------------
__global__ void k_deg_init(int* __restrict__ deg) {
    int i = blockIdx.x * blockDim.x + threadIdx.x;
    if (i < NN) deg[i] = 1;   // self loop
}

__global__ void k_deg_edges(const int* __restrict__ col, int* __restrict__ deg) {
    int e = blockIdx.x * blockDim.x + threadIdx.x;
    if (e < EE) atomicAdd(&deg[col[e]], 1);
}

__global__ void k_dinv(const int* __restrict__ deg, float* __restrict__ dinv) {
    int i = blockIdx.x * blockDim.x + threadIdx.x;
    if (i < NN) dinv[i] = rsqrtf((float)deg[i]);
}

// ---------------------------------------------------------------------------
// Generic tiled SGEMM: C[M,Nn] = act(A[M,K] @ W[K,Nn] + bias)
// 64x64 tile, K-chunk 16, 128 threads, 4x8 per-thread register tile.
// ---------------------------------------------------------------------------
__global__ __launch_bounds__(128)
void sgemm(const float* __restrict__ A, const float* __restrict__ W,
           const float* __restrict__ bias, float* __restrict__ C,
           int M, int K, int Nn, int do_relu)
{
    __shared__ float As[16][64];   // transposed: As[k][m]
    __shared__ float Bs[16][64];

    const int tid = threadIdx.x;
    const int m0 = blockIdx.y * 64;
    const int n0 = blockIdx.x * 64;
    const int ry = tid & 15;       // row group (4 rows)
    const int cx = tid >> 4;       // col group (8 cols)

    float acc[4][8];
#pragma unroll
    for (int i = 0; i < 4; i++)
#pragma unroll
        for (int j = 0; j < 8; j++) acc[i][j] = 0.f;

    for (int k0 = 0; k0 < K; k0 += 16) {
        // load A tile (64 rows x 16 k)
        for (int idx = tid; idx < 64 * 16; idx += 128) {
            int m = idx >> 4, kk = idx & 15;
            int gm = m0 + m, gk = k0 + kk;
            As[kk][m] = (gm < M && gk < K) ? A[(size_t)gm * K + gk] : 0.f;
        }
        // load B tile (16 k x 64 cols)
        for (int idx = tid; idx < 16 * 64; idx += 128) {
            int kk = idx >> 6, n = idx & 63;
            int gk = k0 + kk, gn = n0 + n;
            Bs[kk][n] = (gk < K && gn < Nn) ? W[(size_t)gk * Nn + gn] : 0.f;
        }
        __syncthreads();
#pragma unroll
        for (int k = 0; k < 16; k++) {
            float4 a  = *(const float4*)&As[k][ry * 4];
            float4 b0 = *(const float4*)&Bs[k][cx * 8];
            float4 b1 = *(const float4*)&Bs[k][cx * 8 + 4];
            float av[4] = {a.x, a.y, a.z, a.w};
            float bv[8] = {b0.x, b0.y, b0.z, b0.w, b1.x, b1.y, b1.z, b1.w};
#pragma unroll
            for (int i = 0; i < 4; i++)
#pragma unroll
                for (int j = 0; j < 8; j++) acc[i][j] += av[i] * bv[j];
        }
        __syncthreads();
    }

#pragma unroll
    for (int i = 0; i < 4; i++) {
        int gm = m0 + ry * 4 + i;
        if (gm >= M) continue;
#pragma unroll
        for (int j = 0; j < 8; j++) {
            int gn = n0 + cx * 8 + j;
            if (gn >= Nn) continue;
            float v = acc[i][j] + (bias ? bias[gn] : 0.f);
            if (do_relu) v = fmaxf(v, 0.f);
            C[(size_t)gm * Nn + gn] = v;
        }
    }
}

// ---------------------------------------------------------------------------
// GCN aggregation
// ---------------------------------------------------------------------------
__global__ void k_selfloop(const float* __restrict__ xw, const float* __restrict__ dinv,
                           float* __restrict__ acc)
{
    size_t i = (size_t)blockIdx.x * blockDim.x + threadIdx.x;
    if (i < (size_t)NN * HH) {
        int node = (int)(i >> 7);
        float d = dinv[node];
        acc[i] = xw[i] * d * d;
    }
}

__global__ __launch_bounds__(256)
void k_scatter(const float* __restrict__ xw, const int* __restrict__ row,
               const int* __restrict__ col, const float* __restrict__ dinv,
               float* __restrict__ acc)
{
    int idx = blockIdx.x * blockDim.x + threadIdx.x;
    int e = idx >> 5;
    int lane = idx & 31;
    if (e >= EE) return;
    int s = __ldg(&row[e]);
    int t = __ldg(&col[e]);
    float c = dinv[s] * dinv[t];
    float4 v = ((const float4*)(xw + (size_t)s * HH))[lane];
    float* dst = acc + (size_t)t * HH + lane * 4;
    asm volatile("red.global.add.v4.f32 [%0], {%1, %2, %3, %4};"
                 :: "l"(dst), "f"(v.x * c), "f"(v.y * c), "f"(v.z * c), "f"(v.w * c)
                 : "memory");
}

__global__ void k_bias_relu(const float* __restrict__ acc, const float* __restrict__ b,
                            float* __restrict__ h)
{
    size_t i = (size_t)blockIdx.x * blockDim.x + threadIdx.x;
    if (i < (size_t)NN * HH) h[i] = fmaxf(acc[i] + b[i & (HH - 1)], 0.f);
}

// ---------------------------------------------------------------------------
// Edge MLP: per 64-edge tile compute
//   H1 = relu([h[row] | h[col] | edge_attr] @ W1 + b1)   (64x288 @ 288x128)
//   out = H1 @ W2 + b2                                    (64x128 @ 128x4)
// ---------------------------------------------------------------------------
__global__ __launch_bounds__(128)
void k_edge_mlp(const float* __restrict__ h, const int* __restrict__ row,
                const int* __restrict__ col, const float* __restrict__ ea,
                const float* __restrict__ W1, const float* __restrict__ b1,
                const float* __restrict__ W2, const float* __restrict__ b2,
                float* __restrict__ out)
{
    __shared__ int rows_s[64], cols_s[64];
    __shared__ float As[8][64];        // gathered features, k-major
    __shared__ float Bs[8][128];       // W1 chunk
    __shared__ float H1[64 * 130];     // padded hidden
    __shared__ float W2s[128 * 4];
    __shared__ float b1s[128];

    const int tid = threadIdx.x;
    const int e0 = blockIdx.x * 64;

    if (tid < 64) { rows_s[tid] = row[e0 + tid]; cols_s[tid] = col[e0 + tid]; }
    b1s[tid] = b1[tid];
    for (int i = tid; i < 128 * 4; i += 128) W2s[i] = W2[i];
    __syncthreads();

    const int tx = tid & 15;   // 16 col groups of 8 -> 128
    const int ty = tid >> 4;   // 8 row groups of 8  -> 64

    float acc[8][8];
#pragma unroll
    for (int i = 0; i < 8; i++)
#pragma unroll
        for (int j = 0; j < 8; j++) acc[i][j] = 0.f;

    for (int k0 = 0; k0 < 288; k0 += 8) {
        // gather A tile: 64 edges x 8 features, via float2 (256 units)
#pragma unroll
        for (int it = 0; it < 2; it++) {
            int idx = tid + it * 128;
            int m = idx >> 2;
            int kk = (idx & 3) * 2;
            int k = k0 + kk;
            float2 v;
            if (k < 128) {
                int id = rows_s[m];
                v = *(const float2*)&h[(size_t)id * HH + k];
            } else if (k < 256) {
                int id = cols_s[m];
                v = *(const float2*)&h[(size_t)id * HH + (k - 128)];
            } else {
                v = *(const float2*)&ea[(size_t)(e0 + m) * FE + (k - 256)];
            }
            As[kk][m] = v.x;
            As[kk + 1][m] = v.y;
        }
        // W1 chunk: 8 x 128 via float4 (256 units)
#pragma unroll
        for (int it = 0; it < 2; it++) {
            int idx = tid + it * 128;
            int kk = idx >> 5;
            int n4 = (idx & 31) * 4;
            *(float4*)&Bs[kk][n4] = *(const float4*)&W1[(size_t)(k0 + kk) * HH + n4];
        }
        __syncthreads();
#pragma unroll
        for (int kk = 0; kk < 8; kk++) {
            float4 a0 = *(const float4*)&As[kk][ty * 8];
            float4 a1 = *(const float4*)&As[kk][ty * 8 + 4];
            float4 c0 = *(const float4*)&Bs[kk][tx * 8];
            float4 c1 = *(const float4*)&Bs[kk][tx * 8 + 4];
            float av[8] = {a0.x, a0.y, a0.z, a0.w, a1.x, a1.y, a1.z, a1.w};
            float bv[8] = {c0.x, c0.y, c0.z, c0.w, c1.x, c1.y, c1.z, c1.w};
#pragma unroll
            for (int i = 0; i < 8; i++)
#pragma unroll
                for (int j = 0; j < 8; j++) acc[i][j] += av[i] * bv[j];
        }
        __syncthreads();
    }

    // bias + relu -> H1 (padded stride 130)
#pragma unroll
    for (int i = 0; i < 8; i++) {
        int m = ty * 8 + i;
#pragma unroll
        for (int j = 0; j < 8; j++) {
            int n = tx * 8 + j;
            H1[m * 130 + n] = fmaxf(acc[i][j] + b1s[n], 0.f);
        }
    }
    __syncthreads();

    // second GEMM: each thread produces 2 of the 4 logits for one edge
    int m = tid >> 1;
    int c = (tid & 1) * 2;
    float s0 = 0.f, s1 = 0.f;
#pragma unroll 8
    for (int n = 0; n < 128; n++) {
        float hv = H1[m * 130 + n];
        s0 += hv * W2s[n * 4 + c];
        s1 += hv * W2s[n * 4 + c + 1];
    }
    out[(size_t)(e0 + m) * 4 + c]     = s0 + b2[c];
    out[(size_t)(e0 + m) * 4 + c + 1] = s1 + b2[c + 1];
}

// ---------------------------------------------------------------------------
extern "C" void kernel_launch(void* const* d_in, const int* in_sizes, int n_in,
                              void* d_out, int out_size)
{
    const float* x      = (const float*)d_in[0];
    const int*   ei     = (const int*)  d_in[1];
    const float* ea     = (const float*)d_in[2];
    const float* We     = (const float*)d_in[3];
    const float* be     = (const float*)d_in[4];
    const float* Wc1    = (const float*)d_in[5];
    const float* bc1    = (const float*)d_in[6];
    const float* Wc2    = (const float*)d_in[7];
    const float* bc2    = (const float*)d_in[8];
    const float* Wn1    = (const float*)d_in[9];
    const float* bn1    = (const float*)d_in[10];
    const float* Wn2    = (const float*)d_in[11];
    const float* bn2    = (const float*)d_in[12];
    const float* We1    = (const float*)d_in[13];
    const float* be1    = (const float*)d_in[14];
    const float* We2    = (const float*)d_in[15];
    const float* be2    = (const float*)d_in[16];

    const int* row = ei;
    const int* col = ei + EE;

    float* out_node = (float*)d_out;             // [NN, 12]
    float* out_edge = out_node + (size_t)NN * CN; // [EE, 4]

    float *ph, *pxw, *pacc, *pdinv;
    int* pdeg;
    cudaGetSymbolAddress((void**)&ph,   g_h);
    cudaGetSymbolAddress((void**)&pxw,  g_xw);
    cudaGetSymbolAddress((void**)&pacc, g_acc);
    cudaGetSymbolAddress((void**)&pdinv,g_dinv);
    cudaGetSymbolAddress((void**)&pdeg, g_deg);

    const int T = 256;
    const size_t NH = (size_t)NN * HH;

    // degrees + norm
    k_deg_init<<<(NN + T - 1) / T, T>>>(pdeg);
    k_deg_edges<<<(EE + T - 1) / T, T>>>(col, pdeg);
    k_dinv<<<(NN + T - 1) / T, T>>>(pdeg, pdinv);

    dim3 gemm_blk_h((HH + 63) / 64, (NN + 63) / 64);

    // h = relu(x @ We + be)   (double relu == single)
    sgemm<<<gemm_blk_h, 128>>>(x, We, be, ph, NN, FN, HH, 1);

    // conv1
    sgemm<<<gemm_blk_h, 128>>>(ph, Wc1, nullptr, pxw, NN, HH, HH, 0);
    k_selfloop<<<(int)((NH + T - 1) / T), T>>>(pxw, pdinv, pacc);
    k_scatter<<<(int)(((size_t)EE * 32 + T - 1) / T), T>>>(pxw, row, col, pdinv, pacc);
    k_bias_relu<<<(int)((NH + T - 1) / T), T>>>(pacc, bc1, ph);

    // conv2
    sgemm<<<gemm_blk_h, 128>>>(ph, Wc2, nullptr, pxw, NN, HH, HH, 0);
    k_selfloop<<<(int)((NH + T - 1) / T), T>>>(pxw, pdinv, pacc);
    k_scatter<<<(int)(((size_t)EE * 32 + T - 1) / T), T>>>(pxw, row, col, pdinv, pacc);
    k_bias_relu<<<(int)((NH + T - 1) / T), T>>>(pacc, bc2, ph);

    // node head: t = relu(h @ Wn1 + bn1); logits = t @ Wn2 + bn2
    dim3 gemm_blk_n1((64 + 63) / 64, (NN + 63) / 64);
    sgemm<<<gemm_blk_n1, 128>>>(ph, Wn1, bn1, pxw, NN, HH, 64, 1);
    dim3 gemm_blk_n2((CN + 63) / 64, (NN + 63) / 64);
    sgemm<<<gemm_blk_n2, 128>>>(pxw, Wn2, bn2, out_node, NN, 64, CN, 0);

    // edge MLP
    k_edge_mlp<<<EE / 64, 128>>>(ph, row, col, ea, We1, be1, We2, be2, out_edge);
}

// round 2
// speedup vs baseline: 1.6503x; 1.6503x over previous
#include <cuda_runtime.h>
#include <cuda_bf16.h>
#include <cstdint>

#define NN 100000
#define EE 1000000
#define HH 128
#define FN 64
#define FE 32
#define CN 12
#define CE 4
#define KTOT 288

// ---------------------------------------------------------------------------
// Scratch (device globals — no cudaMalloc allowed)
// ---------------------------------------------------------------------------
__device__ float g_h  [(size_t)NN * HH];
__device__ float g_xw [(size_t)NN * HH];
__device__ float g_acc[(size_t)NN * HH];
__device__ float g_dinv[NN];
__device__ int   g_deg [NN];

__device__ __nv_bfloat16 g_h_hi [(size_t)NN * HH];
__device__ __nv_bfloat16 g_h_lo [(size_t)NN * HH];
__device__ __nv_bfloat16 g_ea_hi[(size_t)EE * FE];
__device__ __nv_bfloat16 g_ea_lo[(size_t)EE * FE];
__device__ __nv_bfloat16 g_w1t_hi[HH * KTOT];
__device__ __nv_bfloat16 g_w1t_lo[HH * KTOT];

// ---------------------------------------------------------------------------
// Degree / normalization
// ---------------------------------------------------------------------------
__global__ void k_deg_init(int* __restrict__ deg) {
    int i = blockIdx.x * blockDim.x + threadIdx.x;
    if (i < NN) deg[i] = 1;
}
__global__ void k_deg_edges(const int* __restrict__ col, int* __restrict__ deg) {
    int e = blockIdx.x * blockDim.x + threadIdx.x;
    if (e < EE) atomicAdd(&deg[col[e]], 1);
}
__global__ void k_dinv(const int* __restrict__ deg, float* __restrict__ dinv) {
    int i = blockIdx.x * blockDim.x + threadIdx.x;
    if (i < NN) dinv[i] = rsqrtf((float)deg[i]);
}

// ---------------------------------------------------------------------------
// Generic tiled fp32 SGEMM (used for small GEMMs): C = act(A @ W + bias)
// ---------------------------------------------------------------------------
__global__ __launch_bounds__(128)
void sgemm(const float* __restrict__ A, const float* __restrict__ W,
           const float* __restrict__ bias, float* __restrict__ C,
           int M, int K, int Nn, int do_relu)
{
    __shared__ float As[16][64];
    __shared__ float Bs[16][64];

    const int tid = threadIdx.x;
    const int m0 = blockIdx.y * 64;
    const int n0 = blockIdx.x * 64;
    const int ry = tid & 15;
    const int cx = tid >> 4;

    float acc[4][8];
#pragma unroll
    for (int i = 0; i < 4; i++)
#pragma unroll
        for (int j = 0; j < 8; j++) acc[i][j] = 0.f;

    for (int k0 = 0; k0 < K; k0 += 16) {
        for (int idx = tid; idx < 64 * 16; idx += 128) {
            int m = idx >> 4, kk = idx & 15;
            int gm = m0 + m, gk = k0 + kk;
            As[kk][m] = (gm < M && gk < K) ? A[(size_t)gm * K + gk] : 0.f;
        }
        for (int idx = tid; idx < 16 * 64; idx += 128) {
            int kk = idx >> 6, n = idx & 63;
            int gk = k0 + kk, gn = n0 + n;
            Bs[kk][n] = (gk < K && gn < Nn) ? W[(size_t)gk * Nn + gn] : 0.f;
        }
        __syncthreads();
#pragma unroll
        for (int k = 0; k < 16; k++) {
            float4 a  = *(const float4*)&As[k][ry * 4];
            float4 b0 = *(const float4*)&Bs[k][cx * 8];
            float4 b1 = *(const float4*)&Bs[k][cx * 8 + 4];
            float av[4] = {a.x, a.y, a.z, a.w};
            float bv[8] = {b0.x, b0.y, b0.z, b0.w, b1.x, b1.y, b1.z, b1.w};
#pragma unroll
            for (int i = 0; i < 4; i++)
#pragma unroll
                for (int j = 0; j < 8; j++) acc[i][j] += av[i] * bv[j];
        }
        __syncthreads();
    }

#pragma unroll
    for (int i = 0; i < 4; i++) {
        int gm = m0 + ry * 4 + i;
        if (gm >= M) continue;
#pragma unroll
        for (int j = 0; j < 8; j++) {
            int gn = n0 + cx * 8 + j;
            if (gn >= Nn) continue;
            float v = acc[i][j] + (bias ? bias[gn] : 0.f);
            if (do_relu) v = fmaxf(v, 0.f);
            C[(size_t)gm * Nn + gn] = v;
        }
    }
}

// ---------------------------------------------------------------------------
// GCN aggregation
// ---------------------------------------------------------------------------
__global__ void k_selfloop(const float* __restrict__ xw, const float* __restrict__ dinv,
                           float* __restrict__ acc)
{
    size_t i = (size_t)blockIdx.x * blockDim.x + threadIdx.x;
    if (i < (size_t)NN * HH) {
        int node = (int)(i >> 7);
        float d = dinv[node];
        acc[i] = xw[i] * d * d;
    }
}

__global__ __launch_bounds__(256)
void k_scatter(const float* __restrict__ xw, const int* __restrict__ row,
               const int* __restrict__ col, const float* __restrict__ dinv,
               float* __restrict__ acc)
{
    int idx = blockIdx.x * blockDim.x + threadIdx.x;
    int e = idx >> 5;
    int lane = idx & 31;
    if (e >= EE) return;
    int s = __ldg(&row[e]);
    int t = __ldg(&col[e]);
    float c = dinv[s] * dinv[t];
    float4 v = ((const float4*)(xw + (size_t)s * HH))[lane];
    float* dst = acc + (size_t)t * HH + lane * 4;
    asm volatile("red.global.add.v4.f32 [%0], {%1, %2, %3, %4};"
                 :: "l"(dst), "f"(v.x * c), "f"(v.y * c), "f"(v.z * c), "f"(v.w * c)
                 : "memory");
}

__global__ void k_bias_relu(const float* __restrict__ acc, const float* __restrict__ b,
                            float* __restrict__ h)
{
    size_t i = (size_t)blockIdx.x * blockDim.x + threadIdx.x;
    if (i < (size_t)NN * HH) h[i] = fmaxf(acc[i] + b[i & (HH - 1)], 0.f);
}

// ---------------------------------------------------------------------------
// bf16 hi/lo splits
// ---------------------------------------------------------------------------
__global__ void k_split(const float* __restrict__ in, __nv_bfloat16* __restrict__ hi,
                        __nv_bfloat16* __restrict__ lo, size_t n)
{
    size_t i = (size_t)blockIdx.x * blockDim.x + threadIdx.x;
    if (i < n) {
        float x = in[i];
        __nv_bfloat16 h = __float2bfloat16_rn(x);
        hi[i] = h;
        lo[i] = __float2bfloat16_rn(x - __bfloat162float(h));
    }
}

// W1 [K=288][N=128] -> W1t [N=128][K=288] split into hi/lo
__global__ void k_split_w1t(const float* __restrict__ W1, __nv_bfloat16* __restrict__ hi,
                            __nv_bfloat16* __restrict__ lo)
{
    int i = blockIdx.x * blockDim.x + threadIdx.x;
    if (i < HH * KTOT) {
        int n = i / KTOT, k = i % KTOT;
        float x = W1[(size_t)k * HH + n];
        __nv_bfloat16 h = __float2bfloat16_rn(x);
        hi[i] = h;
        lo[i] = __float2bfloat16_rn(x - __bfloat162float(h));
    }
}

// ---------------------------------------------------------------------------
// Edge MLP with bf16-split tensor cores.
// CTA: 128 edges, 512 threads, 16 warps (4M x 4N), warp tile 32x32.
// K=288 chunked by 32, cp.async double-buffered swizzled SMEM tiles.
// ---------------------------------------------------------------------------
#define EK_TILE_B 8192           // one 128x32 bf16 tile
#define EK_STAGE_B (4 * EK_TILE_B)
#define EK_EXTRA_B 3584          // rs(512)+cs(512)+b1s(512)+w2s(2048)
#define EK_H1_B (128 * 132 * 4)
#define EK_SMEM_B (EK_EXTRA_B + (EK_H1_B > 2 * EK_STAGE_B ? EK_H1_B : 2 * EK_STAGE_B))

__device__ __forceinline__ void ldsm_x4(uint32_t (&r)[4], uint32_t addr) {
    asm volatile("ldmatrix.sync.aligned.m8n8.x4.shared.b16 {%0,%1,%2,%3}, [%4];"
                 : "=r"(r[0]), "=r"(r[1]), "=r"(r[2]), "=r"(r[3]) : "r"(addr));
}
__device__ __forceinline__ void mma_bf16(float (&d)[4], const uint32_t (&a)[4],
                                         uint32_t b0, uint32_t b1) {
    asm volatile("mma.sync.aligned.m16n8k16.row.col.f32.bf16.bf16.f32 "
                 "{%0,%1,%2,%3},{%4,%5,%6,%7},{%8,%9},{%0,%1,%2,%3};"
                 : "+f"(d[0]), "+f"(d[1]), "+f"(d[2]), "+f"(d[3])
                 : "r"(a[0]), "r"(a[1]), "r"(a[2]), "r"(a[3]), "r"(b0), "r"(b1));
}
__device__ __forceinline__ void cp16(uint32_t saddr, const void* gaddr) {
    asm volatile("cp.async.cg.shared.global [%0], [%1], 16;" :: "r"(saddr), "l"(gaddr));
}
__device__ __forceinline__ uint32_t sw_off(int r, int c) {  // bf16-element tile offset -> bytes
    return (uint32_t)((r * 32 + ((c ^ ((r >> 1) & 3)) << 3)) * 2);
}

__global__ __launch_bounds__(512)
void k_edge_mma(const __nv_bfloat16* __restrict__ h_hi, const __nv_bfloat16* __restrict__ h_lo,
                const __nv_bfloat16* __restrict__ ea_hi, const __nv_bfloat16* __restrict__ ea_lo,
                const __nv_bfloat16* __restrict__ w1t_hi, const __nv_bfloat16* __restrict__ w1t_lo,
                const int* __restrict__ row, const int* __restrict__ col,
                const float* __restrict__ b1, const float* __restrict__ W2,
                const float* __restrict__ b2, float* __restrict__ out)
{
    extern __shared__ char smem_raw[];
    int*   rs  = (int*)smem_raw;            // 128
    int*   cs  = rs + 128;                  // 128
    float* b1s = (float*)(cs + 128);        // 128
    float* w2s = b1s + 128;                 // 512
    char*  uni = (char*)(w2s + 512);
    float* H1  = (float*)uni;               // [128][132], aliases tiles

    const int tid  = threadIdx.x;
    const int lane = tid & 31;
    const int w    = tid >> 5;
    const int wm   = w & 3, wn = w >> 2;
    const int m0   = wm * 32, n0 = wn * 32;
    const int e0   = blockIdx.x * 128;

    if (tid < 128) {
        int eid = min(e0 + tid, EE - 1);
        rs[tid] = row[eid];
        cs[tid] = col[eid];
        b1s[tid] = b1[tid];
    }
    for (int i = tid; i < 512; i += 512) w2s[i] = W2[i];
    __syncthreads();

    // tile bases (shared-space u32)
    uint32_t uni_s = (uint32_t)__cvta_generic_to_shared(uni);
    // per-thread fill coords
    const int fr = tid >> 2;        // 0..127
    const int fc = tid & 3;         // 0..3
    const uint32_t fdst = sw_off(fr, fc);
    const size_t eac = (size_t)min(e0 + fr, EE - 1) * FE + (fc << 3);

    auto fill = [&](int st, int ck) {
        uint32_t base = uni_s + st * EK_STAGE_B;
        const __nv_bfloat16 *ahs, *als;
        if (ck < 8) {
            int id = (ck < 4) ? rs[fr] : cs[fr];
            size_t o = (size_t)id * HH + ((ck & 3) << 5) + (fc << 3);
            ahs = h_hi + o; als = h_lo + o;
        } else {
            ahs = ea_hi + eac; als = ea_lo + eac;
        }
        cp16(base + 0 * EK_TILE_B + fdst, ahs);
        cp16(base + 1 * EK_TILE_B + fdst, als);
        size_t bo = (size_t)fr * KTOT + (ck << 5) + (fc << 3);
        cp16(base + 2 * EK_TILE_B + fdst, w1t_hi + bo);
        cp16(base + 3 * EK_TILE_B + fdst, w1t_lo + bo);
        asm volatile("cp.async.commit_group;");
    };

    float acc[2][4][4];
#pragma unroll
    for (int i = 0; i < 2; i++)
#pragma unroll
        for (int j = 0; j < 4; j++)
#pragma unroll
            for (int k = 0; k < 4; k++) acc[i][j][k] = 0.f;

    fill(0, 0);

    const int gi = lane & 7;
    const int gA_r = (lane >> 3) & 1;   // row-half select for A
    const int gA_c = lane >> 4;         // k-half select for A
    const int gB_r = lane >> 4;         // row-half select for B
    const int gB_c = (lane >> 3) & 1;   // k-half select for B

    for (int ck = 0; ck < 9; ck++) {
        if (ck + 1 < 9) {
            fill((ck + 1) & 1, ck + 1);
            asm volatile("cp.async.wait_group 1;");
        } else {
            asm volatile("cp.async.wait_group 0;");
        }
        __syncthreads();

        uint32_t base = uni_s + (ck & 1) * EK_STAGE_B;
        uint32_t aHiB = base, aLoB = base + EK_TILE_B;
        uint32_t bHiB = base + 2 * EK_TILE_B, bLoB = base + 3 * EK_TILE_B;

#pragma unroll
        for (int step = 0; step < 2; step++) {
            int cbase = step * 2;
            uint32_t a_hi[2][4], a_lo[2][4];
#pragma unroll
            for (int mt = 0; mt < 2; mt++) {
                int r = m0 + mt * 16 + (gA_r << 3) + gi;
                int c = cbase + gA_c;
                uint32_t off = sw_off(r, c);
                ldsm_x4(a_hi[mt], aHiB + off);
                ldsm_x4(a_lo[mt], aLoB + off);
            }
            uint32_t b_hi[4][2], b_lo[4][2];
#pragma unroll
            for (int p = 0; p < 2; p++) {
                int r = n0 + (p << 4) + (gB_r << 3) + gi;
                int c = cbase + gB_c;
                uint32_t off = sw_off(r, c);
                uint32_t t4[4];
                ldsm_x4(t4, bHiB + off);
                b_hi[2 * p][0] = t4[0]; b_hi[2 * p][1] = t4[1];
                b_hi[2 * p + 1][0] = t4[2]; b_hi[2 * p + 1][1] = t4[3];
                ldsm_x4(t4, bLoB + off);
                b_lo[2 * p][0] = t4[0]; b_lo[2 * p][1] = t4[1];
                b_lo[2 * p + 1][0] = t4[2]; b_lo[2 * p + 1][1] = t4[3];
            }
#pragma unroll
            for (int mt = 0; mt < 2; mt++)
#pragma unroll
                for (int nt = 0; nt < 4; nt++) {
                    mma_bf16(acc[mt][nt], a_hi[mt], b_hi[nt][0], b_hi[nt][1]);
                    mma_bf16(acc[mt][nt], a_hi[mt], b_lo[nt][0], b_lo[nt][1]);
                    mma_bf16(acc[mt][nt], a_lo[mt], b_hi[nt][0], b_hi[nt][1]);
                }
        }
        __syncthreads();
    }

    // bias + relu -> H1 (tiles are dead; barrier above guarantees all reads done)
#pragma unroll
    for (int mt = 0; mt < 2; mt++)
#pragma unroll
        for (int nt = 0; nt < 4; nt++) {
            int r0 = m0 + mt * 16 + (lane >> 2);
            int c0 = n0 + nt * 8 + ((lane & 3) << 1);
            H1[r0 * 132 + c0]           = fmaxf(acc[mt][nt][0] + b1s[c0], 0.f);
            H1[r0 * 132 + c0 + 1]       = fmaxf(acc[mt][nt][1] + b1s[c0 + 1], 0.f);
            H1[(r0 + 8) * 132 + c0]     = fmaxf(acc[mt][nt][2] + b1s[c0], 0.f);
            H1[(r0 + 8) * 132 + c0 + 1] = fmaxf(acc[mt][nt][3] + b1s[c0 + 1], 0.f);
        }
    __syncthreads();

    // second GEMM: 512 threads -> 128 edges x 4 logits
    int m = tid >> 2, c = tid & 3;
    float s = 0.f;
#pragma unroll 8
    for (int n = 0; n < 128; n++) s += H1[m * 132 + n] * w2s[n * 4 + c];
    if (e0 + m < EE) out[(size_t)(e0 + m) * 4 + c] = s + b2[c];
}

// ---------------------------------------------------------------------------
extern "C" void kernel_launch(void* const* d_in, const int* in_sizes, int n_in,
                              void* d_out, int out_size)
{
    const float* x   = (const float*)d_in[0];
    const int*   ei  = (const int*)  d_in[1];
    const float* ea  = (const float*)d_in[2];
    const float* We  = (const float*)d_in[3];
    const float* be  = (const float*)d_in[4];
    const float* Wc1 = (const float*)d_in[5];
    const float* bc1 = (const float*)d_in[6];
    const float* Wc2 = (const float*)d_in[7];
    const float* bc2 = (const float*)d_in[8];
    const float* Wn1 = (const float*)d_in[9];
    const float* bn1 = (const float*)d_in[10];
    const float* Wn2 = (const float*)d_in[11];
    const float* bn2 = (const float*)d_in[12];
    const float* We1 = (const float*)d_in[13];
    const float* be1 = (const float*)d_in[14];
    const float* We2 = (const float*)d_in[15];
    const float* be2 = (const float*)d_in[16];

    const int* row = ei;
    const int* col = ei + EE;

    float* out_node = (float*)d_out;
    float* out_edge = out_node + (size_t)NN * CN;

    float *ph, *pxw, *pacc, *pdinv;
    int* pdeg;
    __nv_bfloat16 *phh, *phl, *peh, *pel, *pwh, *pwl;
    cudaGetSymbolAddress((void**)&ph,   g_h);
    cudaGetSymbolAddress((void**)&pxw,  g_xw);
    cudaGetSymbolAddress((void**)&pacc, g_acc);
    cudaGetSymbolAddress((void**)&pdinv,g_dinv);
    cudaGetSymbolAddress((void**)&pdeg, g_deg);
    cudaGetSymbolAddress((void**)&phh,  g_h_hi);
    cudaGetSymbolAddress((void**)&phl,  g_h_lo);
    cudaGetSymbolAddress((void**)&peh,  g_ea_hi);
    cudaGetSymbolAddress((void**)&pel,  g_ea_lo);
    cudaGetSymbolAddress((void**)&pwh,  g_w1t_hi);
    cudaGetSymbolAddress((void**)&pwl,  g_w1t_lo);

    static bool attr_set = false;
    if (!attr_set) {
        cudaFuncSetAttribute(k_edge_mma, cudaFuncAttributeMaxDynamicSharedMemorySize,
                             EK_SMEM_B);
        attr_set = true;
    }

    const int T = 256;
    const size_t NH = (size_t)NN * HH;

    // degrees + norm
    k_deg_init<<<(NN + T - 1) / T, T>>>(pdeg);
    k_deg_edges<<<(EE + T - 1) / T, T>>>(col, pdeg);
    k_dinv<<<(NN + T - 1) / T, T>>>(pdeg, pdinv);

    dim3 gemm_blk_h((HH + 63) / 64, (NN + 63) / 64);

    // h = relu(x @ We + be)
    sgemm<<<gemm_blk_h, 128>>>(x, We, be, ph, NN, FN, HH, 1);

    // conv1
    sgemm<<<gemm_blk_h, 128>>>(ph, Wc1, nullptr, pxw, NN, HH, HH, 0);
    k_selfloop<<<(int)((NH + T - 1) / T), T>>>(pxw, pdinv, pacc);
    k_scatter<<<(int)(((size_t)EE * 32 + T - 1) / T), T>>>(pxw, row, col, pdinv, pacc);
    k_bias_relu<<<(int)((NH + T - 1) / T), T>>>(pacc, bc1, ph);

    // conv2
    sgemm<<<gemm_blk_h, 128>>>(ph, Wc2, nullptr, pxw, NN, HH, HH, 0);
    k_selfloop<<<(int)((NH + T - 1) / T), T>>>(pxw, pdinv, pacc);
    k_scatter<<<(int)(((size_t)EE * 32 + T - 1) / T), T>>>(pxw, row, col, pdinv, pacc);
    k_bias_relu<<<(int)((NH + T - 1) / T), T>>>(pacc, bc2, ph);

    // node head
    dim3 gemm_blk_n1(1, (NN + 63) / 64);
    sgemm<<<gemm_blk_n1, 128>>>(ph, Wn1, bn1, pxw, NN, HH, 64, 1);
    dim3 gemm_blk_n2(1, (NN + 63) / 64);
    sgemm<<<gemm_blk_n2, 128>>>(pxw, Wn2, bn2, out_node, NN, 64, CN, 0);

    // bf16 splits for edge MLP
    k_split<<<(int)((NH + T - 1) / T), T>>>(ph, phh, phl, NH);
    k_split<<<(int)(((size_t)EE * FE + T - 1) / T), T>>>(ea, peh, pel, (size_t)EE * FE);
    k_split_w1t<<<(HH * KTOT + T - 1) / T, T>>>(We1, pwh, pwl);

    // edge MLP (tensor cores)
    k_edge_mma<<<(EE + 127) / 128, 512, EK_SMEM_B>>>(
        phh, phl, peh, pel, pwh, pwl, row, col, be1, We2, be2, out_edge);
}

// round 3
// speedup vs baseline: 2.0877x; 1.2651x over previous
#include <cuda_runtime.h>
#include <cuda_fp16.h>
#include <cstdint>

#define NN 100000
#define EE 1000000
#define HH 128
#define FN 64
#define FE 32
#define CN 12
#define CE 4
#define KTOT 288
#define NT_EDGE ((EE + 127) / 128)   // 7813
#define GRID_EDGE 148

// ---------------------------------------------------------------------------
// Scratch (device globals — no cudaMalloc allowed)
// ---------------------------------------------------------------------------
__device__ float g_h  [(size_t)NN * HH];
__device__ float g_xw [(size_t)NN * HH];
__device__ float g_acc[(size_t)NN * HH];
__device__ float g_dinv[NN];
__device__ int   g_deg [NN];

__device__ __align__(16) __half g_h16 [(size_t)NN * HH];
__device__ __align__(16) __half g_ea16[(size_t)EE * FE];
__device__ __align__(16) __half g_w1h [HH * KTOT];
__device__ __align__(16) __half g_w1l [HH * KTOT];

// ---------------------------------------------------------------------------
// Degree / normalization
// ---------------------------------------------------------------------------
__global__ void k_deg_init(int* __restrict__ deg) {
    int i = blockIdx.x * blockDim.x + threadIdx.x;
    if (i < NN) deg[i] = 1;
}
__global__ void k_deg_edges(const int* __restrict__ col, int* __restrict__ deg) {
    int e = blockIdx.x * blockDim.x + threadIdx.x;
    if (e < EE) atomicAdd(&deg[col[e]], 1);
}
__global__ void k_dinv(const int* __restrict__ deg, float* __restrict__ dinv) {
    int i = blockIdx.x * blockDim.x + threadIdx.x;
    if (i < NN) dinv[i] = rsqrtf((float)deg[i]);
}

// ---------------------------------------------------------------------------
// Tiled fp32 SGEMM: C = act(A@W + bias); optional fused selfloop acc = C*dinv^2
// ---------------------------------------------------------------------------
__global__ __launch_bounds__(128)
void sgemm(const float* __restrict__ A, const float* __restrict__ W,
           const float* __restrict__ bias, float* __restrict__ C,
           int M, int K, int Nn, int do_relu,
           const float* __restrict__ dinv, float* __restrict__ acc_out)
{
    __shared__ float As[16][64];
    __shared__ float Bs[16][64];

    const int tid = threadIdx.x;
    const int m0 = blockIdx.y * 64;
    const int n0 = blockIdx.x * 64;
    const int ry = tid & 15;
    const int cx = tid >> 4;

    float acc[4][8];
#pragma unroll
    for (int i = 0; i < 4; i++)
#pragma unroll
        for (int j = 0; j < 8; j++) acc[i][j] = 0.f;

    for (int k0 = 0; k0 < K; k0 += 16) {
        for (int idx = tid; idx < 64 * 16; idx += 128) {
            int m = idx >> 4, kk = idx & 15;
            int gm = m0 + m, gk = k0 + kk;
            As[kk][m] = (gm < M && gk < K) ? A[(size_t)gm * K + gk] : 0.f;
        }
        for (int idx = tid; idx < 16 * 64; idx += 128) {
            int kk = idx >> 6, n = idx & 63;
            int gk = k0 + kk, gn = n0 + n;
            Bs[kk][n] = (gk < K && gn < Nn) ? W[(size_t)gk * Nn + gn] : 0.f;
        }
        __syncthreads();
#pragma unroll
        for (int k = 0; k < 16; k++) {
            float4 a  = *(const float4*)&As[k][ry * 4];
            float4 b0 = *(const float4*)&Bs[k][cx * 8];
            float4 b1 = *(const float4*)&Bs[k][cx * 8 + 4];
            float av[4] = {a.x, a.y, a.z, a.w};
            float bv[8] = {b0.x, b0.y, b0.z, b0.w, b1.x, b1.y, b1.z, b1.w};
#pragma unroll
            for (int i = 0; i < 4; i++)
#pragma unroll
                for (int j = 0; j < 8; j++) acc[i][j] += av[i] * bv[j];
        }
        __syncthreads();
    }

#pragma unroll
    for (int i = 0; i < 4; i++) {
        int gm = m0 + ry * 4 + i;
        if (gm >= M) continue;
        float d2 = 0.f;
        if (acc_out) { float d = dinv[gm]; d2 = d * d; }
#pragma unroll
        for (int j = 0; j < 8; j++) {
            int gn = n0 + cx * 8 + j;
            if (gn >= Nn) continue;
            float v = acc[i][j] + (bias ? bias[gn] : 0.f);
            if (do_relu) v = fmaxf(v, 0.f);
            C[(size_t)gm * Nn + gn] = v;
            if (acc_out) acc_out[(size_t)gm * Nn + gn] = v * d2;
        }
    }
}

// ---------------------------------------------------------------------------
// GCN aggregation
// ---------------------------------------------------------------------------
__global__ __launch_bounds__(256)
void k_scatter(const float* __restrict__ xw, const int* __restrict__ row,
               const int* __restrict__ col, const float* __restrict__ dinv,
               float* __restrict__ acc)
{
    int idx = blockIdx.x * blockDim.x + threadIdx.x;
    int e = idx >> 5;
    int lane = idx & 31;
    if (e >= EE) return;
    int s = __ldg(&row[e]);
    int t = __ldg(&col[e]);
    float c = dinv[s] * dinv[t];
    float4 v = ((const float4*)(xw + (size_t)s * HH))[lane];
    float* dst = acc + (size_t)t * HH + lane * 4;
    asm volatile("red.global.add.v4.f32 [%0], {%1, %2, %3, %4};"
                 :: "l"(dst), "f"(v.x * c), "f"(v.y * c), "f"(v.z * c), "f"(v.w * c)
                 : "memory");
}

__global__ void k_bias_relu(const float* __restrict__ acc, const float* __restrict__ b,
                            float* __restrict__ h)
{
    size_t i = (size_t)blockIdx.x * blockDim.x + threadIdx.x;
    if (i < (size_t)NN * HH) h[i] = fmaxf(acc[i] + b[i & (HH - 1)], 0.f);
}

__global__ void k_bias_relu_h16(const float* __restrict__ acc, const float* __restrict__ b,
                                float* __restrict__ h, __half* __restrict__ h16)
{
    size_t i = (size_t)blockIdx.x * blockDim.x + threadIdx.x;
    if (i < (size_t)NN * HH) {
        float v = fmaxf(acc[i] + b[i & (HH - 1)], 0.f);
        h[i] = v;
        h16[i] = __float2half_rn(v);
    }
}

__global__ void k_tof16(const float* __restrict__ in, __half* __restrict__ o, size_t n)
{
    size_t i = (size_t)blockIdx.x * blockDim.x + threadIdx.x;
    if (i < n) o[i] = __float2half_rn(in[i]);
}

// W1 [K=288][N=128] -> W1t [N=128][K=288] fp16 hi/lo split
__global__ void k_split_w1t(const float* __restrict__ W1, __half* __restrict__ hi,
                            __half* __restrict__ lo)
{
    int i = blockIdx.x * blockDim.x + threadIdx.x;
    if (i < HH * KTOT) {
        int n = i / KTOT, k = i % KTOT;
        float x = W1[(size_t)k * HH + n];
        __half h = __float2half_rn(x);
        hi[i] = h;
        lo[i] = __float2half_rn(x - __half2float(h));
    }
}

// ---------------------------------------------------------------------------
// Edge MLP: persistent CTAs, W1t fp16 hi/lo resident in SMEM, A fp16 gathered,
// 2 mma passes (A*Bhi + A*Blo), register-fragment second GEMM.
// ---------------------------------------------------------------------------
#define BBLK 16384                      // one [128n x 64k] fp16 block
#define SM_BH    0
#define SM_BL    (SM_BH + 5 * BBLK)     // 81920
#define SM_AST   (SM_BL + 5 * BBLK)     // 163840, 2 x 16384
#define SM_RS    (SM_AST + 2 * 16384)   // 196608, 2 x 128 int
#define SM_CS    (SM_RS + 1024)
#define SM_B1    (SM_CS + 1024)         // 128 f
#define SM_W2    (SM_B1 + 512)          // 512 f
#define SM_B2    (SM_W2 + 2048)         // 4 f
#define SM_OP    (SM_B2 + 16)           // out_part [4][128][4] f
#define SM_END   (SM_OP + 8192)         // 209424

__device__ __forceinline__ uint32_t sw128(uint32_t byte_off) {
    return byte_off ^ ((byte_off >> 3) & 0x70);
}
__device__ __forceinline__ void ldsm_x4(uint32_t (&r)[4], uint32_t addr) {
    asm volatile("ldmatrix.sync.aligned.m8n8.x4.shared.b16 {%0,%1,%2,%3}, [%4];"
                 : "=r"(r[0]), "=r"(r[1]), "=r"(r[2]), "=r"(r[3]) : "r"(addr));
}
__device__ __forceinline__ void mma_f16(float (&d)[4], const uint32_t (&a)[4],
                                        uint32_t b0, uint32_t b1) {
    asm volatile("mma.sync.aligned.m16n8k16.row.col.f32.f16.f16.f32 "
                 "{%0,%1,%2,%3},{%4,%5,%6,%7},{%8,%9},{%0,%1,%2,%3};"
                 : "+f"(d[0]), "+f"(d[1]), "+f"(d[2]), "+f"(d[3])
                 : "r"(a[0]), "r"(a[1]), "r"(a[2]), "r"(a[3]), "r"(b0), "r"(b1));
}
__device__ __forceinline__ void cp16(uint32_t saddr, const void* gaddr) {
    asm volatile("cp.async.cg.shared.global [%0], [%1], 16;" :: "r"(saddr), "l"(gaddr));
}

__global__ __launch_bounds__(512, 1)
void k_edge(const __half* __restrict__ h16, const __half* __restrict__ ea16,
            const __half* __restrict__ w1h, const __half* __restrict__ w1l,
            const int* __restrict__ row, const int* __restrict__ col,
            const float* __restrict__ b1, const float* __restrict__ W2,
            const float* __restrict__ b2, float* __restrict__ out)
{
    extern __shared__ char sm[];
    uint32_t smb = (uint32_t)__cvta_generic_to_shared(sm);
    int*   rs2 = (int*)(sm + SM_RS);
    int*   cs2 = (int*)(sm + SM_CS);
    float* b1s = (float*)(sm + SM_B1);
    float* w2s = (float*)(sm + SM_W2);
    float* b2s = (float*)(sm + SM_B2);
    float* opart = (float*)(sm + SM_OP);

    const int tid  = threadIdx.x;
    const int lane = tid & 31;
    const int w    = tid >> 5;
    const int wm   = w & 3, wn = w >> 2;
    const int m0   = wm * 32, n0 = wn * 32;

    // small tables
    if (tid < 128) b1s[tid] = b1[tid];
    if (tid < 512) w2s[tid] = W2[tid];
    if (tid < 4)   b2s[tid] = b2[tid];

    // resident B: W1t fp16 hi/lo, 5 blocks of [128 x 64] (block4 half-filled)
    for (int idx = tid; idx < 4608; idx += 512) {
        int b, n, fc;
        if (idx < 4096) { b = idx >> 10; n = (idx >> 3) & 127; fc = idx & 7; }
        else            { b = 4; n = (idx - 4096) >> 2; fc = (idx - 4096) & 3; }
        uint32_t dst = sw128((uint32_t)(n * 128 + fc * 16));
        const __half* src = w1h + (size_t)n * KTOT + b * 64 + fc * 8;
        cp16(smb + SM_BH + b * BBLK + dst, src);
        const __half* srcl = w1l + (size_t)n * KTOT + b * 64 + fc * 8;
        cp16(smb + SM_BL + b * BBLK + dst, srcl);
    }
    asm volatile("cp.async.commit_group;");

    // indices for first tile
    int t0 = blockIdx.x;
    if (tid < 128 && t0 < NT_EDGE) {
        int e = min(t0 * 128 + tid, EE - 1);
        rs2[tid] = row[e];
        cs2[tid] = col[e];
    }
    asm volatile("cp.async.wait_group 0;" ::: "memory");
    __syncthreads();

    const int gi   = lane & 7;
    const int gA_r = (lane >> 3) & 1;
    const int gA_c = lane >> 4;
    const int gB_r = lane >> 4;
    const int gB_c = (lane >> 3) & 1;

    // fill helper (inline lambda)
    auto fill = [&](int k, int c, int stage) {
        int ib = k & 1;
        uint32_t abase = smb + SM_AST + stage * 16384;
        int t = blockIdx.x + k * GRID_EDGE;
        int e0 = t * 128;
        if (c < 4) {
#pragma unroll
            for (int it = 0; it < 2; it++) {
                int idx = tid + it * 512;
                int fr = idx >> 3, fc = idx & 7;
                int node = (c < 2) ? rs2[ib * 128 + fr] : cs2[ib * 128 + fr];
                int koff = ((c & 1) << 6) + fc * 8;
                cp16(abase + sw128((uint32_t)(fr * 128 + fc * 16)),
                     h16 + (size_t)node * HH + koff);
            }
        } else {
            int fr = tid >> 2, fc = tid & 3;
            int e = min(e0 + fr, EE - 1);
            cp16(abase + sw128((uint32_t)(fr * 128 + fc * 16)),
                 ea16 + (size_t)e * FE + fc * 8);
        }
        asm volatile("cp.async.commit_group;");
    };

    // prologue fill: tile k=0, chunk 0, stage 0
    int nLocal = 0;
    for (int t = blockIdx.x; t < NT_EDGE; t += GRID_EDGE) nLocal++;
    if (nLocal == 0) return;
    fill(0, 0, 0);

    int q = 0;   // global chunk counter (stage = q & 1)
    for (int k = 0; k < nLocal; k++) {
        int t = blockIdx.x + k * GRID_EDGE;
        int e0 = t * 128;
        // prefetch indices for tile k+1
        if (k + 1 < nLocal && tid < 128) {
            int tn = t + GRID_EDGE;
            int e = min(tn * 128 + tid, EE - 1);
            rs2[((k + 1) & 1) * 128 + tid] = row[e];
            cs2[((k + 1) & 1) * 128 + tid] = col[e];
        }

        float acc[2][4][4];
#pragma unroll
        for (int i = 0; i < 2; i++)
#pragma unroll
            for (int j = 0; j < 4; j++)
#pragma unroll
                for (int x = 0; x < 4; x++) acc[i][j][x] = 0.f;

        for (int c = 0; c < 5; c++, q++) {
            // wait for fill(q), barrier so all warps done with stage (q-1)&1
            asm volatile("cp.async.wait_group 0;" ::: "memory");
            __syncthreads();
            // issue next fill
            if (c < 4) fill(k, c + 1, (q + 1) & 1);
            else if (k + 1 < nLocal) fill(k + 1, 0, (q + 1) & 1);

            // consume chunk c from stage q&1
            uint32_t abase = smb + SM_AST + (q & 1) * 16384;
            int nks = (c == 4) ? 2 : 4;
            for (int ks = 0; ks < nks; ks++) {
                uint32_t a[2][4];
#pragma unroll
                for (int mt = 0; mt < 2; mt++) {
                    int r = m0 + mt * 16 + (gA_r << 3) + gi;
                    ldsm_x4(a[mt], abase + sw128((uint32_t)(r * 128 + (ks * 2 + gA_c) * 16)));
                }
                uint32_t bh[4][2], bl[4][2];
#pragma unroll
                for (int p = 0; p < 2; p++) {
                    int n = n0 + (p << 4) + (gB_r << 3) + gi;
                    uint32_t off = (uint32_t)(c * BBLK) + sw128((uint32_t)(n * 128 + (ks * 2 + gB_c) * 16));
                    uint32_t t4[4];
                    ldsm_x4(t4, smb + SM_BH + off);
                    bh[2 * p][0] = t4[0]; bh[2 * p][1] = t4[1];
                    bh[2 * p + 1][0] = t4[2]; bh[2 * p + 1][1] = t4[3];
                    ldsm_x4(t4, smb + SM_BL + off);
                    bl[2 * p][0] = t4[0]; bl[2 * p][1] = t4[1];
                    bl[2 * p + 1][0] = t4[2]; bl[2 * p + 1][1] = t4[3];
                }
#pragma unroll
                for (int mt = 0; mt < 2; mt++)
#pragma unroll
                    for (int nt = 0; nt < 4; nt++) {
                        mma_f16(acc[mt][nt], a[mt], bh[nt][0], bh[nt][1]);
                        mma_f16(acc[mt][nt], a[mt], bl[nt][0], bl[nt][1]);
                    }
            }
        }

        // ----- epilogue: bias+relu on fragments, 128x4 GEMM, reduce -----
        float p[4][4];
#pragma unroll
        for (int i = 0; i < 4; i++)
#pragma unroll
            for (int j = 0; j < 4; j++) p[i][j] = 0.f;

#pragma unroll
        for (int mt = 0; mt < 2; mt++)
#pragma unroll
            for (int hf = 0; hf < 2; hf++) {
                int ri = mt * 2 + hf;
#pragma unroll
                for (int nt = 0; nt < 4; nt++)
#pragma unroll
                    for (int e = 0; e < 2; e++) {
                        int colg = n0 + nt * 8 + (lane & 3) * 2 + e;
                        float h1 = fmaxf(acc[mt][nt][hf * 2 + e] + b1s[colg], 0.f);
#pragma unroll
                        for (int cc = 0; cc < 4; cc++)
                            p[ri][cc] += h1 * w2s[colg * 4 + cc];
                    }
            }
        // reduce over the 4 lanes sharing the same rows (lane & 3)
#pragma unroll
        for (int i = 0; i < 4; i++)
#pragma unroll
            for (int cc = 0; cc < 4; cc++) {
                p[i][cc] += __shfl_xor_sync(0xffffffffu, p[i][cc], 1);
                p[i][cc] += __shfl_xor_sync(0xffffffffu, p[i][cc], 2);
            }
        if ((lane & 3) == 0) {
#pragma unroll
            for (int mt = 0; mt < 2; mt++)
#pragma unroll
                for (int hf = 0; hf < 2; hf++) {
                    int r = m0 + mt * 16 + (lane >> 2) + hf * 8;
#pragma unroll
                    for (int cc = 0; cc < 4; cc++)
                        opart[wn * 512 + r * 4 + cc] = p[mt * 2 + hf][cc];
                }
        }
        __syncthreads();
        {
            int r = tid >> 2, cc = tid & 3;
            float s = opart[tid] + opart[512 + tid] + opart[1024 + tid] + opart[1536 + tid]
                    + b2s[cc];
            if (e0 + r < EE) out[(size_t)(e0 + r) * 4 + cc] = s;
        }
        __syncthreads();
    }
}

// ---------------------------------------------------------------------------
extern "C" void kernel_launch(void* const* d_in, const int* in_sizes, int n_in,
                              void* d_out, int out_size)
{
    const float* x   = (const float*)d_in[0];
    const int*   ei  = (const int*)  d_in[1];
    const float* ea  = (const float*)d_in[2];
    const float* We  = (const float*)d_in[3];
    const float* be  = (const float*)d_in[4];
    const float* Wc1 = (const float*)d_in[5];
    const float* bc1 = (const float*)d_in[6];
    const float* Wc2 = (const float*)d_in[7];
    const float* bc2 = (const float*)d_in[8];
    const float* Wn1 = (const float*)d_in[9];
    const float* bn1 = (const float*)d_in[10];
    const float* Wn2 = (const float*)d_in[11];
    const float* bn2 = (const float*)d_in[12];
    const float* We1 = (const float*)d_in[13];
    const float* be1 = (const float*)d_in[14];
    const float* We2 = (const float*)d_in[15];
    const float* be2 = (const float*)d_in[16];

    const int* row = ei;
    const int* col = ei + EE;

    float* out_node = (float*)d_out;
    float* out_edge = out_node + (size_t)NN * CN;

    float *ph, *pxw, *pacc, *pdinv;
    int* pdeg;
    __half *ph16, *pea16, *pw1h, *pw1l;
    cudaGetSymbolAddress((void**)&ph,    g_h);
    cudaGetSymbolAddress((void**)&pxw,   g_xw);
    cudaGetSymbolAddress((void**)&pacc,  g_acc);
    cudaGetSymbolAddress((void**)&pdinv, g_dinv);
    cudaGetSymbolAddress((void**)&pdeg,  g_deg);
    cudaGetSymbolAddress((void**)&ph16,  g_h16);
    cudaGetSymbolAddress((void**)&pea16, g_ea16);
    cudaGetSymbolAddress((void**)&pw1h,  g_w1h);
    cudaGetSymbolAddress((void**)&pw1l,  g_w1l);

    static bool attr_set = false;
    if (!attr_set) {
        cudaFuncSetAttribute(k_edge, cudaFuncAttributeMaxDynamicSharedMemorySize, SM_END);
        attr_set = true;
    }

    const int T = 256;
    const size_t NH = (size_t)NN * HH;

    // degrees + norm
    k_deg_init<<<(NN + T - 1) / T, T>>>(pdeg);
    k_deg_edges<<<(EE + T - 1) / T, T>>>(col, pdeg);
    k_dinv<<<(NN + T - 1) / T, T>>>(pdeg, pdinv);

    // conversions that don't depend on h (overlap-friendly, graph order is fine)
    k_tof16<<<(int)(((size_t)EE * FE + T - 1) / T), T>>>(ea, pea16, (size_t)EE * FE);
    k_split_w1t<<<(HH * KTOT + T - 1) / T, T>>>(We1, pw1h, pw1l);

    dim3 gemm_blk_h((HH + 63) / 64, (NN + 63) / 64);

    // h = relu(x @ We + be)
    sgemm<<<gemm_blk_h, 128>>>(x, We, be, ph, NN, FN, HH, 1, nullptr, nullptr);

    // conv1 (selfloop fused into sgemm epilogue)
    sgemm<<<gemm_blk_h, 128>>>(ph, Wc1, nullptr, pxw, NN, HH, HH, 0, pdinv, pacc);
    k_scatter<<<(int)(((size_t)EE * 32 + T - 1) / T), T>>>(pxw, row, col, pdinv, pacc);
    k_bias_relu<<<(int)((NH + T - 1) / T), T>>>(pacc, bc1, ph);

    // conv2
    sgemm<<<gemm_blk_h, 128>>>(ph, Wc2, nullptr, pxw, NN, HH, HH, 0, pdinv, pacc);
    k_scatter<<<(int)(((size_t)EE * 32 + T - 1) / T), T>>>(pxw, row, col, pdinv, pacc);
    k_bias_relu_h16<<<(int)((NH + T - 1) / T), T>>>(pacc, bc2, ph, ph16);

    // node head
    dim3 gemm_blk_n1(1, (NN + 63) / 64);
    sgemm<<<gemm_blk_n1, 128>>>(ph, Wn1, bn1, pxw, NN, HH, 64, 1, nullptr, nullptr);
    dim3 gemm_blk_n2(1, (NN + 63) / 64);
    sgemm<<<gemm_blk_n2, 128>>>(pxw, Wn2, bn2, out_node, NN, 64, CN, 0, nullptr, nullptr);

    // edge MLP (persistent, resident W1t)
    k_edge<<<GRID_EDGE, 512, SM_END>>>(ph16, pea16, pw1h, pw1l, row, col,
                                       be1, We2, be2, out_edge);
}

// round 6
// speedup vs baseline: 2.4118x; 1.1552x over previous
#include <cuda_runtime.h>
#include <cuda_fp16.h>
#include <cstdint>
#include <cstring>

#define NN 100000
#define EE 1000000
#define HH 128
#define FN 64
#define FE 32
#define CN 12
#define CE 4
#define KTOT 288
#define NT_EDGE ((EE + 127) / 128)   // 7813
#define GRID_EDGE 148

// ---------------------------------------------------------------------------
// Scratch (device globals — no cudaMalloc allowed)
// ---------------------------------------------------------------------------
__device__ float g_h  [(size_t)NN * HH];
__device__ float g_xw [(size_t)NN * HH];
__device__ float g_acc[(size_t)NN * HH];
__device__ float g_dinv[NN];
__device__ int   g_deg [NN];

__device__ __align__(16) __half g_h16 [(size_t)NN * HH];
__device__ __align__(16) __half g_ea16[(size_t)EE * FE];
__device__ __align__(16) __half g_w1h [HH * KTOT];

// ---------------------------------------------------------------------------
// Degree / normalization
// ---------------------------------------------------------------------------
__global__ void k_deg_init(int* __restrict__ deg) {
    int i = blockIdx.x * blockDim.x + threadIdx.x;
    if (i < NN) deg[i] = 1;
}
__global__ void k_deg_edges(const int* __restrict__ col, int* __restrict__ deg) {
    int e = blockIdx.x * blockDim.x + threadIdx.x;
    if (e < EE) atomicAdd(&deg[col[e]], 1);
}
__global__ void k_dinv(const int* __restrict__ deg, float* __restrict__ dinv) {
    int i = blockIdx.x * blockDim.x + threadIdx.x;
    if (i < NN) dinv[i] = rsqrtf((float)deg[i]);
}

// ---------------------------------------------------------------------------
// Tiled fp32 SGEMM: C = act(A@W + bias); optional fused selfloop acc = C*dinv^2
// ---------------------------------------------------------------------------
__global__ __launch_bounds__(128)
void sgemm(const float* __restrict__ A, const float* __restrict__ W,
           const float* __restrict__ bias, float* __restrict__ C,
           int M, int K, int Nn, int do_relu,
           const float* __restrict__ dinv, float* __restrict__ acc_out)
{
    __shared__ float As[16][64];
    __shared__ float Bs[16][64];

    const int tid = threadIdx.x;
    const int m0 = blockIdx.y * 64;
    const int n0 = blockIdx.x * 64;
    const int ry = tid & 15;
    const int cx = tid >> 4;

    float acc[4][8];
#pragma unroll
    for (int i = 0; i < 4; i++)
#pragma unroll
        for (int j = 0; j < 8; j++) acc[i][j] = 0.f;

    for (int k0 = 0; k0 < K; k0 += 16) {
        for (int idx = tid; idx < 64 * 16; idx += 128) {
            int m = idx >> 4, kk = idx & 15;
            int gm = m0 + m, gk = k0 + kk;
            As[kk][m] = (gm < M && gk < K) ? A[(size_t)gm * K + gk] : 0.f;
        }
        for (int idx = tid; idx < 16 * 64; idx += 128) {
            int kk = idx >> 6, n = idx & 63;
            int gk = k0 + kk, gn = n0 + n;
            Bs[kk][n] = (gk < K && gn < Nn) ? W[(size_t)gk * Nn + gn] : 0.f;
        }
        __syncthreads();
#pragma unroll
        for (int k = 0; k < 16; k++) {
            float4 a  = *(const float4*)&As[k][ry * 4];
            float4 b0 = *(const float4*)&Bs[k][cx * 8];
            float4 b1 = *(const float4*)&Bs[k][cx * 8 + 4];
            float av[4] = {a.x, a.y, a.z, a.w};
            float bv[8] = {b0.x, b0.y, b0.z, b0.w, b1.x, b1.y, b1.z, b1.w};
#pragma unroll
            for (int i = 0; i < 4; i++)
#pragma unroll
                for (int j = 0; j < 8; j++) acc[i][j] += av[i] * bv[j];
        }
        __syncthreads();
    }

#pragma unroll
    for (int i = 0; i < 4; i++) {
        int gm = m0 + ry * 4 + i;
        if (gm >= M) continue;
        float d2 = 0.f;
        if (acc_out) { float d = dinv[gm]; d2 = d * d; }
#pragma unroll
        for (int j = 0; j < 8; j++) {
            int gn = n0 + cx * 8 + j;
            if (gn >= Nn) continue;
            float v = acc[i][j] + (bias ? bias[gn] : 0.f);
            if (do_relu) v = fmaxf(v, 0.f);
            C[(size_t)gm * Nn + gn] = v;
            if (acc_out) acc_out[(size_t)gm * Nn + gn] = v * d2;
        }
    }
}

// ---------------------------------------------------------------------------
// GCN aggregation
// ---------------------------------------------------------------------------
__global__ __launch_bounds__(256)
void k_scatter(const float* __restrict__ xw, const int* __restrict__ row,
               const int* __restrict__ col, const float* __restrict__ dinv,
               float* __restrict__ acc)
{
    int idx = blockIdx.x * blockDim.x + threadIdx.x;
    int e = idx >> 5;
    int lane = idx & 31;
    if (e >= EE) return;
    int s = __ldg(&row[e]);
    int t = __ldg(&col[e]);
    float c = dinv[s] * dinv[t];
    float4 v = ((const float4*)(xw + (size_t)s * HH))[lane];
    float* dst = acc + (size_t)t * HH + lane * 4;
    asm volatile("red.global.add.v4.f32 [%0], {%1, %2, %3, %4};"
                 :: "l"(dst), "f"(v.x * c), "f"(v.y * c), "f"(v.z * c), "f"(v.w * c)
                 : "memory");
}

__global__ void k_bias_relu(const float* __restrict__ acc, const float* __restrict__ b,
                            float* __restrict__ h)
{
    size_t i = (size_t)blockIdx.x * blockDim.x + threadIdx.x;
    if (i < (size_t)NN * HH) h[i] = fmaxf(acc[i] + b[i & (HH - 1)], 0.f);
}

__global__ void k_bias_relu_h16(const float* __restrict__ acc, const float* __restrict__ b,
                                float* __restrict__ h, __half* __restrict__ h16)
{
    size_t i = (size_t)blockIdx.x * blockDim.x + threadIdx.x;
    if (i < (size_t)NN * HH) {
        float v = fmaxf(acc[i] + b[i & (HH - 1)], 0.f);
        h[i] = v;
        h16[i] = __float2half_rn(v);
    }
}

// vectorized fp32 -> fp16, 8 elements / thread (n must be multiple of 8)
__global__ void k_tof16_v(const float4* __restrict__ in, uint4* __restrict__ o, size_t n8)
{
    size_t i = (size_t)blockIdx.x * blockDim.x + threadIdx.x;
    if (i >= n8) return;
    float4 a = in[i * 2];
    float4 b = in[i * 2 + 1];
    __half2 h[4];
    h[0] = __floats2half2_rn(a.x, a.y);
    h[1] = __floats2half2_rn(a.z, a.w);
    h[2] = __floats2half2_rn(b.x, b.y);
    h[3] = __floats2half2_rn(b.z, b.w);
    o[i] = *reinterpret_cast<const uint4*>(h);
}

// W1 [K=288][N=128] -> W1t [N=128][K=288] fp16
__global__ void k_w1t16(const float* __restrict__ W1, __half* __restrict__ o)
{
    int i = blockIdx.x * blockDim.x + threadIdx.x;
    if (i < HH * KTOT) {
        int n = i / KTOT, k = i % KTOT;
        o[i] = __float2half_rn(W1[(size_t)k * HH + n]);
    }
}

// ---------------------------------------------------------------------------
// Edge MLP: persistent CTAs, W1t fp16 resident in SMEM, A fp16 gathered,
// 4-stage cp.async pipeline, single mma pass, register-fragment 2nd GEMM.
// ---------------------------------------------------------------------------
#define BBLK 16384                      // one [128n x 64k] fp16 block
#define NSTG 4
#define SM_BH    0
#define SM_AST   (SM_BH + 5 * BBLK)     // 81920, 4 x 16384
#define SM_RS    (SM_AST + NSTG * 16384)// 147456
#define SM_CS    (SM_RS + 1024)
#define SM_B1    (SM_CS + 1024)         // 128 f
#define SM_W2    (SM_B1 + 512)          // 512 f
#define SM_B2    (SM_W2 + 2048)         // 4 f
#define SM_OP    (SM_B2 + 16)           // out_part [4][128][4] f
#define SM_END   (SM_OP + 8192)         // 160272

__device__ __forceinline__ uint32_t sw128(uint32_t byte_off) {
    return byte_off ^ ((byte_off >> 3) & 0x70);
}
__device__ __forceinline__ void ldsm_x4(uint32_t (&r)[4], uint32_t addr) {
    asm volatile("ldmatrix.sync.aligned.m8n8.x4.shared.b16 {%0,%1,%2,%3}, [%4];"
                 : "=r"(r[0]), "=r"(r[1]), "=r"(r[2]), "=r"(r[3]) : "r"(addr));
}
__device__ __forceinline__ void mma_f16(float (&d)[4], const uint32_t (&a)[4],
                                        uint32_t b0, uint32_t b1) {
    asm volatile("mma.sync.aligned.m16n8k16.row.col.f32.f16.f16.f32 "
                 "{%0,%1,%2,%3},{%4,%5,%6,%7},{%8,%9},{%0,%1,%2,%3};"
                 : "+f"(d[0]), "+f"(d[1]), "+f"(d[2]), "+f"(d[3])
                 : "r"(a[0]), "r"(a[1]), "r"(a[2]), "r"(a[3]), "r"(b0), "r"(b1));
}
__device__ __forceinline__ void cp16(uint32_t saddr, const void* gaddr) {
    asm volatile("cp.async.cg.shared.global [%0], [%1], 16;" :: "r"(saddr), "l"(gaddr));
}

__global__ __launch_bounds__(512, 1)
void k_edge(const __half* __restrict__ h16, const __half* __restrict__ ea16,
            const __half* __restrict__ w1h,
            const int* __restrict__ row, const int* __restrict__ col,
            const float* __restrict__ b1, const float* __restrict__ W2,
            const float* __restrict__ b2, float* __restrict__ out)
{
    extern __shared__ char sm[];
    uint32_t smb = (uint32_t)__cvta_generic_to_shared(sm);
    int*   rs2 = (int*)(sm + SM_RS);
    int*   cs2 = (int*)(sm + SM_CS);
    float* b1s = (float*)(sm + SM_B1);
    float* w2s = (float*)(sm + SM_W2);
    float* b2s = (float*)(sm + SM_B2);
    float* opart = (float*)(sm + SM_OP);

    const int tid  = threadIdx.x;
    const int lane = tid & 31;
    const int w    = tid >> 5;
    const int wm   = w & 3, wn = w >> 2;
    const int m0   = wm * 32, n0 = wn * 32;

    // small tables
    if (tid < 128) b1s[tid] = b1[tid];
    if (tid < 512) w2s[tid] = W2[tid];
    if (tid < 4)   b2s[tid] = b2[tid];

    int nLocal = 0;
    for (int t = blockIdx.x; t < NT_EDGE; t += GRID_EDGE) nLocal++;
    if (nLocal == 0) return;
    const int totalQ = nLocal * 5;

    // resident B: W1t fp16, 5 blocks of [128 x 64] (block4 half: k 256..287)
    for (int idx = tid; idx < 4608; idx += 512) {
        int b, n, fc;
        if (idx < 4096) { b = idx >> 10; n = (idx >> 3) & 127; fc = idx & 7; }
        else            { b = 4; n = (idx - 4096) >> 2; fc = (idx - 4096) & 3; }
        uint32_t dst = sw128((uint32_t)(n * 128 + fc * 16));
        cp16(smb + SM_BH + b * BBLK + dst, w1h + (size_t)n * KTOT + b * 64 + fc * 8);
    }
    asm volatile("cp.async.commit_group;");

    // indices for tile 0
    if (tid < 128) {
        int e = min(blockIdx.x * 128 + tid, EE - 1);
        rs2[tid] = row[e];
        cs2[tid] = col[e];
    }
    __syncthreads();   // indices visible before fills

    // fill chunk q (global), stage q % NSTG
    auto fill = [&](int q) {
        int k = q / 5, c = q - k * 5;
        int ib = k & 1;
        uint32_t abase = smb + SM_AST + (q & (NSTG - 1)) * 16384;
        if (c < 4) {
#pragma unroll
            for (int it = 0; it < 2; it++) {
                int idx = tid + it * 512;
                int fr = idx >> 3, fc = idx & 7;
                int node = (c < 2) ? rs2[ib * 128 + fr] : cs2[ib * 128 + fr];
                int koff = ((c & 1) << 6) + fc * 8;
                cp16(abase + sw128((uint32_t)(fr * 128 + fc * 16)),
                     h16 + (size_t)node * HH + koff);
            }
        } else {
            int fr = tid >> 2, fc = tid & 3;
            int e0 = (blockIdx.x + k * GRID_EDGE) * 128;
            int e = min(e0 + fr, EE - 1);
            cp16(abase + sw128((uint32_t)(fr * 128 + fc * 16)),
                 ea16 + (size_t)e * FE + fc * 8);
        }
        asm volatile("cp.async.commit_group;");
    };

    // prologue: 3 chunks in flight
    fill(0); fill(1); fill(2);

    const int gi   = lane & 7;
    const int gA_r = (lane >> 3) & 1;
    const int gA_c = lane >> 4;
    const int gB_r = lane >> 4;
    const int gB_c = (lane >> 3) & 1;

    float acc[2][4][4];

    for (int q = 0; q < totalQ; q++) {
        int k = q / 5, c = q - k * 5;

        asm volatile("cp.async.wait_group 2;" ::: "memory");
        __syncthreads();
        if (q + 3 < totalQ) fill(q + 3);

        if (c == 0) {
            // prefetch indices for tile k+1 (needed first at q = k*5+2's fill)
            if (k + 1 < nLocal && tid < 128) {
                int e = min((blockIdx.x + (k + 1) * GRID_EDGE) * 128 + tid, EE - 1);
                rs2[((k + 1) & 1) * 128 + tid] = row[e];
                cs2[((k + 1) & 1) * 128 + tid] = col[e];
            }
#pragma unroll
            for (int i = 0; i < 2; i++)
#pragma unroll
                for (int j = 0; j < 4; j++)
#pragma unroll
                    for (int x = 0; x < 4; x++) acc[i][j][x] = 0.f;
        }

        // consume chunk c from stage q % NSTG
        uint32_t abase = smb + SM_AST + (q & (NSTG - 1)) * 16384;
        int nks = (c == 4) ? 2 : 4;
        for (int ks = 0; ks < nks; ks++) {
            uint32_t a[2][4];
#pragma unroll
            for (int mt = 0; mt < 2; mt++) {
                int r = m0 + mt * 16 + (gA_r << 3) + gi;
                ldsm_x4(a[mt], abase + sw128((uint32_t)(r * 128 + (ks * 2 + gA_c) * 16)));
            }
            uint32_t bh[4][2];
#pragma unroll
            for (int p = 0; p < 2; p++) {
                int n = n0 + (p << 4) + (gB_r << 3) + gi;
                uint32_t off = (uint32_t)(c * BBLK) + sw128((uint32_t)(n * 128 + (ks * 2 + gB_c) * 16));
                uint32_t t4[4];
                ldsm_x4(t4, smb + SM_BH + off);
                bh[2 * p][0] = t4[0]; bh[2 * p][1] = t4[1];
                bh[2 * p + 1][0] = t4[2]; bh[2 * p + 1][1] = t4[3];
            }
#pragma unroll
            for (int mt = 0; mt < 2; mt++)
#pragma unroll
                for (int nt = 0; nt < 4; nt++)
                    mma_f16(acc[mt][nt], a[mt], bh[nt][0], bh[nt][1]);
        }

        if (c == 4) {
            // ----- epilogue: bias+relu on fragments, 128x4 GEMM, reduce -----
            int e0 = (blockIdx.x + k * GRID_EDGE) * 128;
            float p[4][4];
#pragma unroll
            for (int i = 0; i < 4; i++)
#pragma unroll
                for (int j = 0; j < 4; j++) p[i][j] = 0.f;

#pragma unroll
            for (int mt = 0; mt < 2; mt++)
#pragma unroll
                for (int hf = 0; hf < 2; hf++) {
                    int ri = mt * 2 + hf;
#pragma unroll
                    for (int nt = 0; nt < 4; nt++)
#pragma unroll
                        for (int e = 0; e < 2; e++) {
                            int colg = n0 + nt * 8 + (lane & 3) * 2 + e;
                            float h1 = fmaxf(acc[mt][nt][hf * 2 + e] + b1s[colg], 0.f);
#pragma unroll
                            for (int cc = 0; cc < 4; cc++)
                                p[ri][cc] += h1 * w2s[colg * 4 + cc];
                        }
                }
#pragma unroll
            for (int i = 0; i < 4; i++)
#pragma unroll
                for (int cc = 0; cc < 4; cc++) {
                    p[i][cc] += __shfl_xor_sync(0xffffffffu, p[i][cc], 1);
                    p[i][cc] += __shfl_xor_sync(0xffffffffu, p[i][cc], 2);
                }
            if ((lane & 3) == 0) {
#pragma unroll
                for (int mt = 0; mt < 2; mt++)
#pragma unroll
                    for (int hf = 0; hf < 2; hf++) {
                        int r = m0 + mt * 16 + (lane >> 2) + hf * 8;
#pragma unroll
                        for (int cc = 0; cc < 4; cc++)
                            opart[wn * 512 + r * 4 + cc] = p[mt * 2 + hf][cc];
                    }
            }
            __syncthreads();
            {
                int r = tid >> 2, cc = tid & 3;
                float s = opart[tid] + opart[512 + tid] + opart[1024 + tid]
                        + opart[1536 + tid] + b2s[cc];
                if (e0 + r < EE) out[(size_t)(e0 + r) * 4 + cc] = s;
            }
            __syncthreads();
        }
    }
}

// ---------------------------------------------------------------------------
extern "C" void kernel_launch(void* const* d_in, const int* in_sizes, int n_in,
                              void* d_out, int out_size)
{
    const float* x   = (const float*)d_in[0];
    const int*   ei  = (const int*)  d_in[1];
    const float* ea  = (const float*)d_in[2];
    const float* We  = (const float*)d_in[3];
    const float* be  = (const float*)d_in[4];
    const float* Wc1 = (const float*)d_in[5];
    const float* bc1 = (const float*)d_in[6];
    const float* Wc2 = (const float*)d_in[7];
    const float* bc2 = (const float*)d_in[8];
    const float* Wn1 = (const float*)d_in[9];
    const float* bn1 = (const float*)d_in[10];
    const float* Wn2 = (const float*)d_in[11];
    const float* bn2 = (const float*)d_in[12];
    const float* We1 = (const float*)d_in[13];
    const float* be1 = (const float*)d_in[14];
    const float* We2 = (const float*)d_in[15];
    const float* be2 = (const float*)d_in[16];

    const int* row = ei;
    const int* col = ei + EE;

    float* out_node = (float*)d_out;
    float* out_edge = out_node + (size_t)NN * CN;

    float *ph, *pxw, *pacc, *pdinv;
    int* pdeg;
    __half *ph16, *pea16, *pw1h;
    cudaGetSymbolAddress((void**)&ph,    g_h);
    cudaGetSymbolAddress((void**)&pxw,   g_xw);
    cudaGetSymbolAddress((void**)&pacc,  g_acc);
    cudaGetSymbolAddress((void**)&pdinv, g_dinv);
    cudaGetSymbolAddress((void**)&pdeg,  g_deg);
    cudaGetSymbolAddress((void**)&ph16,  g_h16);
    cudaGetSymbolAddress((void**)&pea16, g_ea16);
    cudaGetSymbolAddress((void**)&pw1h,  g_w1h);

    static bool attr_set = false;
    if (!attr_set) {
        cudaFuncSetAttribute(k_edge, cudaFuncAttributeMaxDynamicSharedMemorySize, SM_END);
        attr_set = true;
    }

    const int T = 256;
    const size_t NH = (size_t)NN * HH;

    // degrees + norm
    k_deg_init<<<(NN + T - 1) / T, T>>>(pdeg);
    k_deg_edges<<<(EE + T - 1) / T, T>>>(col, pdeg);
    k_dinv<<<(NN + T - 1) / T, T>>>(pdeg, pdinv);

    // conversions that don't depend on h
    {
        size_t n8 = (size_t)EE * FE / 8;
        k_tof16_v<<<(int)((n8 + T - 1) / T), T>>>((const float4*)ea, (uint4*)pea16, n8);
    }
    k_w1t16<<<(HH * KTOT + T - 1) / T, T>>>(We1, pw1h);

    dim3 gemm_blk_h((HH + 63) / 64, (NN + 63) / 64);

    // h = relu(x @ We + be)
    sgemm<<<gemm_blk_h, 128>>>(x, We, be, ph, NN, FN, HH, 1, nullptr, nullptr);

    // conv1 (selfloop fused into sgemm epilogue)
    sgemm<<<gemm_blk_h, 128>>>(ph, Wc1, nullptr, pxw, NN, HH, HH, 0, pdinv, pacc);
    k_scatter<<<(int)(((size_t)EE * 32 + T - 1) / T), T>>>(pxw, row, col, pdinv, pacc);
    k_bias_relu<<<(int)((NH + T - 1) / T), T>>>(pacc, bc1, ph);

    // conv2
    sgemm<<<gemm_blk_h, 128>>>(ph, Wc2, nullptr, pxw, NN, HH, HH, 0, pdinv, pacc);
    k_scatter<<<(int)(((size_t)EE * 32 + T - 1) / T), T>>>(pxw, row, col, pdinv, pacc);
    k_bias_relu_h16<<<(int)((NH + T - 1) / T), T>>>(pacc, bc2, ph, ph16);

    // node head
    dim3 gemm_blk_n1(1, (NN + 63) / 64);
    sgemm<<<gemm_blk_n1, 128>>>(ph, Wn1, bn1, pxw, NN, HH, 64, 1, nullptr, nullptr);
    dim3 gemm_blk_n2(1, (NN + 63) / 64);
    sgemm<<<gemm_blk_n2, 128>>>(pxw, Wn2, bn2, out_node, NN, 64, CN, 0, nullptr, nullptr);

    // edge MLP (persistent, resident W1t, single-pass fp16 mma)
    k_edge<<<GRID_EDGE, 512, SM_END>>>(ph16, pea16, pw1h, row, col,
                                       be1, We2, be2, out_edge);
}

// round 7
// speedup vs baseline: 3.1902x; 1.3227x over previous
#include <cuda_runtime.h>
#include <cuda_fp16.h>
#include <cstdint>

#define NN 100000
#define EE 1000000
#define HH 128
#define FN 64
#define FE 32
#define CN 12
#define CE 4
#define KTOT 288
#define NT_EDGE ((EE + 127) / 128)   // 7813
#define GRID_P 148

// ---------------------------------------------------------------------------
// Scratch (device globals — no cudaMalloc allowed)
// ---------------------------------------------------------------------------
__device__ float g_xw [(size_t)NN * HH];
__device__ float g_acc[(size_t)NN * HH];
__device__ float g_dinv[NN];
__device__ int   g_deg [NN];

__device__ __align__(16) __half g_xh [(size_t)NN * FN];
__device__ __align__(16) __half g_xl [(size_t)NN * FN];
__device__ __align__(16) __half g_hh [(size_t)NN * HH];
__device__ __align__(16) __half g_hl [(size_t)NN * HH];
__device__ __align__(16) __half g_th [(size_t)NN * 64];
__device__ __align__(16) __half g_tl [(size_t)NN * 64];
__device__ __align__(16) __half g_ea16[(size_t)EE * FE];
__device__ __align__(16) __half g_w1h [HH * KTOT];

// node-path weight transposes (hi/lo), N padded to 128 rows
__device__ __align__(16) __half g_wWe_h[128 * 64],  g_wWe_l[128 * 64];
__device__ __align__(16) __half g_wC1_h[128 * 128], g_wC1_l[128 * 128];
__device__ __align__(16) __half g_wC2_h[128 * 128], g_wC2_l[128 * 128];
__device__ __align__(16) __half g_wN1_h[128 * 128], g_wN1_l[128 * 128];
__device__ __align__(16) __half g_wN2_h[128 * 64],  g_wN2_l[128 * 64];

// ---------------------------------------------------------------------------
// Degree / normalization
// ---------------------------------------------------------------------------
__global__ void k_deg_init(int* __restrict__ deg) {
    int i = blockIdx.x * blockDim.x + threadIdx.x;
    if (i < NN) deg[i] = 1;
}
__global__ void k_deg_edges(const int* __restrict__ col, int* __restrict__ deg) {
    int e = blockIdx.x * blockDim.x + threadIdx.x;
    if (e < EE) atomicAdd(&deg[col[e]], 1);
}
__global__ void k_dinv(const int* __restrict__ deg, float* __restrict__ dinv) {
    int i = blockIdx.x * blockDim.x + threadIdx.x;
    if (i < NN) dinv[i] = rsqrtf((float)deg[i]);
}

// ---------------------------------------------------------------------------
// splits
// ---------------------------------------------------------------------------
__global__ void k_splitA(const float* __restrict__ in, __half* __restrict__ hi,
                         __half* __restrict__ lo, size_t n)
{
    size_t i = (size_t)blockIdx.x * blockDim.x + threadIdx.x;
    if (i < n) {
        float x = in[i];
        __half h = __float2half_rn(x);
        hi[i] = h;
        lo[i] = __float2half_rn(x - __half2float(h));
    }
}

// W [K][Nn] -> Wt hi/lo [128][K], rows n>=Nn zeroed
__global__ void k_splitWt(const float* __restrict__ W, __half* __restrict__ hi,
                          __half* __restrict__ lo, int K, int Nn)
{
    int i = blockIdx.x * blockDim.x + threadIdx.x;
    if (i < 128 * K) {
        int n = i / K, k = i % K;
        float x = (n < Nn) ? W[(size_t)k * Nn + n] : 0.f;
        __half h = __float2half_rn(x);
        hi[i] = h;
        lo[i] = __float2half_rn(x - __half2float(h));
    }
}

// vectorized fp32 -> fp16, 8 elements / thread
__global__ void k_tof16_v(const float4* __restrict__ in, uint4* __restrict__ o, size_t n8)
{
    size_t i = (size_t)blockIdx.x * blockDim.x + threadIdx.x;
    if (i >= n8) return;
    float4 a = in[i * 2];
    float4 b = in[i * 2 + 1];
    __half2 h[4];
    h[0] = __floats2half2_rn(a.x, a.y);
    h[1] = __floats2half2_rn(a.z, a.w);
    h[2] = __floats2half2_rn(b.x, b.y);
    h[3] = __floats2half2_rn(b.z, b.w);
    o[i] = *reinterpret_cast<const uint4*>(h);
}

// W1 [K=288][N=128] -> W1t [N=128][K=288] fp16 (edge MLP)
__global__ void k_w1t16(const float* __restrict__ W1, __half* __restrict__ o)
{
    int i = blockIdx.x * blockDim.x + threadIdx.x;
    if (i < HH * KTOT) {
        int n = i / KTOT, k = i % KTOT;
        o[i] = __float2half_rn(W1[(size_t)k * HH + n]);
    }
}

// ---------------------------------------------------------------------------
// GCN aggregation
// ---------------------------------------------------------------------------
__global__ __launch_bounds__(256)
void k_scatter(const float* __restrict__ xw, const int* __restrict__ row,
               const int* __restrict__ col, const float* __restrict__ dinv,
               float* __restrict__ acc)
{
    int idx = blockIdx.x * blockDim.x + threadIdx.x;
    int e = idx >> 5;
    int lane = idx & 31;
    if (e >= EE) return;
    int s = __ldg(&row[e]);
    int t = __ldg(&col[e]);
    float c = dinv[s] * dinv[t];
    float4 v = ((const float4*)(xw + (size_t)s * HH))[lane];
    float* dst = acc + (size_t)t * HH + lane * 4;
    asm volatile("red.global.add.v4.f32 [%0], {%1, %2, %3, %4};"
                 :: "l"(dst), "f"(v.x * c), "f"(v.y * c), "f"(v.z * c), "f"(v.w * c)
                 : "memory");
}

// acc + bias -> relu -> hi/lo fp16 split
__global__ void k_bias_relu_split(const float* __restrict__ acc, const float* __restrict__ b,
                                  __half* __restrict__ hh, __half* __restrict__ hl)
{
    size_t i = (size_t)blockIdx.x * blockDim.x + threadIdx.x;
    if (i < (size_t)NN * HH) {
        float v = fmaxf(acc[i] + b[i & (HH - 1)], 0.f);
        __half h = __float2half_rn(v);
        hh[i] = h;
        hl[i] = __float2half_rn(v - __half2float(h));
    }
}

// ---------------------------------------------------------------------------
// mma helpers
// ---------------------------------------------------------------------------
__device__ __forceinline__ uint32_t sw128(uint32_t byte_off) {
    return byte_off ^ ((byte_off >> 3) & 0x70);
}
__device__ __forceinline__ void ldsm_x4(uint32_t (&r)[4], uint32_t addr) {
    asm volatile("ldmatrix.sync.aligned.m8n8.x4.shared.b16 {%0,%1,%2,%3}, [%4];"
                 : "=r"(r[0]), "=r"(r[1]), "=r"(r[2]), "=r"(r[3]) : "r"(addr));
}
__device__ __forceinline__ void mma_f16(float (&d)[4], const uint32_t (&a)[4],
                                        uint32_t b0, uint32_t b1) {
    asm volatile("mma.sync.aligned.m16n8k16.row.col.f32.f16.f16.f32 "
                 "{%0,%1,%2,%3},{%4,%5,%6,%7},{%8,%9},{%0,%1,%2,%3};"
                 : "+f"(d[0]), "+f"(d[1]), "+f"(d[2]), "+f"(d[3])
                 : "r"(a[0]), "r"(a[1]), "r"(a[2]), "r"(a[3]), "r"(b0), "r"(b1));
}
__device__ __forceinline__ void cp16(uint32_t saddr, const void* gaddr) {
    asm volatile("cp.async.cg.shared.global [%0], [%1], 16;" :: "r"(saddr), "l"(gaddr));
}

// ---------------------------------------------------------------------------
// Unified node-path GEMM: persistent, split-fp16 3-pass (Ah*Bh + Ah*Bl + Al*Bh).
// CTA tile 128m x 128n, warp tile 32x32, K = KCH*64, A streamed (3 stages),
// B (Wt hi/lo) resident.  EPI: 0=embed relu+split  1=conv (+selfloop acc)
//                               2=head1 relu+split (N=64)  3=head2 (N=12)
// ---------------------------------------------------------------------------
#define MM_SM_B   0                       // 2*KCH blocks of 16384 (max 64 KB)
#define MM_SM_A   65536                   // 3 stages x 32768
#define MM_SM_BIAS (65536 + 3 * 32768)    // 163840, 128 f
#define MM_SM_END (MM_SM_BIAS + 512)      // 164352

template<int KCH, int EPI>
__global__ __launch_bounds__(512, 1)
void k_mm(const __half* __restrict__ Ah, const __half* __restrict__ Al,
          const __half* __restrict__ Bth, const __half* __restrict__ Btl,
          const float* __restrict__ bias, const float* __restrict__ dinv,
          float* __restrict__ outF, float* __restrict__ outAcc,
          __half* __restrict__ outH, __half* __restrict__ outL,
          int M, int Nn)
{
    constexpr int K = KCH * 64;
    extern __shared__ char sm[];
    uint32_t smb = (uint32_t)__cvta_generic_to_shared(sm);
    float* b1s = (float*)(sm + MM_SM_BIAS);

    const int tid  = threadIdx.x;
    const int lane = tid & 31;
    const int w    = tid >> 5;
    const int wm   = w & 3, wn = w >> 2;
    const int m0   = wm * 32, n0 = wn * 32;

    const int NT = (M + 127) / 128;
    int nLocal = 0;
    for (int t = blockIdx.x; t < NT; t += GRID_P) nLocal++;
    if (nLocal == 0) return;
    const int totalQ = nLocal * KCH;

    // resident B: blocks b = chunk*2 + hilo, each [128n x 64k]
    for (int idx = tid; idx < 2 * KCH * 1024; idx += 512) {
        int b = idx >> 10, rem = idx & 1023;
        int n = rem >> 3, fc = rem & 7;
        int cb = b >> 1, hl = b & 1;
        const __half* src = (hl ? Btl : Bth) + (size_t)n * K + cb * 64 + fc * 8;
        cp16(smb + MM_SM_B + b * 16384 + sw128((uint32_t)(n * 128 + fc * 16)), src);
    }
    asm volatile("cp.async.commit_group;");

    if (tid < 128) b1s[tid] = (bias && tid < Nn) ? bias[tid] : 0.f;
    __syncthreads();

    auto fill = [&](int q) {
        int k = q / KCH, c = q - k * KCH;
        int m0g = (blockIdx.x + k * GRID_P) * 128;
        uint32_t abase = smb + MM_SM_A + (q % 3) * 32768;
#pragma unroll
        for (int it = 0; it < 2; it++) {
            int idx = tid + it * 512;
            int fr = idx >> 3, fc = idx & 7;
            int gm = min(m0g + fr, M - 1);
            size_t so = (size_t)gm * K + c * 64 + fc * 8;
            uint32_t d = sw128((uint32_t)(fr * 128 + fc * 16));
            cp16(abase + d, Ah + so);
            cp16(abase + 16384 + d, Al + so);
        }
        asm volatile("cp.async.commit_group;");
    };

    fill(0);
    if (totalQ > 1) fill(1);

    const int gi   = lane & 7;
    const int gA_r = (lane >> 3) & 1;
    const int gA_c = lane >> 4;
    const int gB_r = lane >> 4;
    const int gB_c = (lane >> 3) & 1;

    float acc[2][4][4];

    for (int q = 0; q < totalQ; q++) {
        int k = q / KCH, c = q - k * KCH;

        if (q + 1 < totalQ) { asm volatile("cp.async.wait_group 1;" ::: "memory"); }
        else                { asm volatile("cp.async.wait_group 0;" ::: "memory"); }
        __syncthreads();
        if (q + 2 < totalQ) fill(q + 2);

        if (c == 0) {
#pragma unroll
            for (int i = 0; i < 2; i++)
#pragma unroll
                for (int j = 0; j < 4; j++)
#pragma unroll
                    for (int x = 0; x < 4; x++) acc[i][j][x] = 0.f;
        }

        uint32_t abase = smb + MM_SM_A + (q % 3) * 32768;
        uint32_t bhB = smb + MM_SM_B + (c * 2) * 16384;
        uint32_t blB = bhB + 16384;
#pragma unroll
        for (int ks = 0; ks < 4; ks++) {
            uint32_t ah[2][4], al[2][4];
#pragma unroll
            for (int mt = 0; mt < 2; mt++) {
                int r = m0 + mt * 16 + (gA_r << 3) + gi;
                uint32_t off = sw128((uint32_t)(r * 128 + (ks * 2 + gA_c) * 16));
                ldsm_x4(ah[mt], abase + off);
                ldsm_x4(al[mt], abase + 16384 + off);
            }
            uint32_t bh[4][2], bl[4][2];
#pragma unroll
            for (int p = 0; p < 2; p++) {
                int n = n0 + (p << 4) + (gB_r << 3) + gi;
                uint32_t off = sw128((uint32_t)(n * 128 + (ks * 2 + gB_c) * 16));
                uint32_t t4[4];
                ldsm_x4(t4, bhB + off);
                bh[2 * p][0] = t4[0]; bh[2 * p][1] = t4[1];
                bh[2 * p + 1][0] = t4[2]; bh[2 * p + 1][1] = t4[3];
                ldsm_x4(t4, blB + off);
                bl[2 * p][0] = t4[0]; bl[2 * p][1] = t4[1];
                bl[2 * p + 1][0] = t4[2]; bl[2 * p + 1][1] = t4[3];
            }
#pragma unroll
            for (int mt = 0; mt < 2; mt++)
#pragma unroll
                for (int nt = 0; nt < 4; nt++) {
                    mma_f16(acc[mt][nt], ah[mt], bh[nt][0], bh[nt][1]);
                    mma_f16(acc[mt][nt], ah[mt], bl[nt][0], bl[nt][1]);
                    mma_f16(acc[mt][nt], al[mt], bh[nt][0], bh[nt][1]);
                }
        }

        if (c == KCH - 1) {
            int m0g = (blockIdx.x + k * GRID_P) * 128;
#pragma unroll
            for (int mt = 0; mt < 2; mt++)
#pragma unroll
                for (int hf = 0; hf < 2; hf++) {
                    int gm = m0g + m0 + mt * 16 + (lane >> 2) + hf * 8;
                    if (gm >= M) continue;
                    float d2 = 0.f;
                    if (EPI == 1) { float d = dinv[gm]; d2 = d * d; }
#pragma unroll
                    for (int nt = 0; nt < 4; nt++)
#pragma unroll
                        for (int e = 0; e < 2; e++) {
                            int n = n0 + nt * 8 + (lane & 3) * 2 + e;
                            float v = acc[mt][nt][hf * 2 + e];
                            if (EPI == 0) {
                                v = fmaxf(v + b1s[n], 0.f);
                                __half h = __float2half_rn(v);
                                outH[(size_t)gm * 128 + n] = h;
                                outL[(size_t)gm * 128 + n] =
                                    __float2half_rn(v - __half2float(h));
                            } else if (EPI == 1) {
                                outF[(size_t)gm * 128 + n] = v;
                                outAcc[(size_t)gm * 128 + n] = v * d2;
                            } else if (EPI == 2) {
                                if (n < 64) {
                                    v = fmaxf(v + b1s[n], 0.f);
                                    __half h = __float2half_rn(v);
                                    outH[(size_t)gm * 64 + n] = h;
                                    outL[(size_t)gm * 64 + n] =
                                        __float2half_rn(v - __half2float(h));
                                }
                            } else {
                                if (n < CN) outF[(size_t)gm * CN + n] = v + b1s[n];
                            }
                        }
                }
        }
    }
}

// ---------------------------------------------------------------------------
// Edge MLP: persistent CTAs, W1t fp16 resident in SMEM, A fp16 gathered,
// 4-stage cp.async pipeline, single mma pass, register-fragment 2nd GEMM.
// ---------------------------------------------------------------------------
#define BBLK 16384                      // one [128n x 64k] fp16 block
#define NSTG 4
#define SM_BH    0
#define SM_AST   (SM_BH + 5 * BBLK)     // 81920, 4 x 16384
#define SM_RS    (SM_AST + NSTG * 16384)// 147456
#define SM_CS    (SM_RS + 1024)
#define SM_B1    (SM_CS + 1024)
#define SM_W2    (SM_B1 + 512)
#define SM_B2    (SM_W2 + 2048)
#define SM_OP    (SM_B2 + 16)
#define SM_END   (SM_OP + 8192)         // 160272

__global__ __launch_bounds__(512, 1)
void k_edge(const __half* __restrict__ h16, const __half* __restrict__ ea16,
            const __half* __restrict__ w1h,
            const int* __restrict__ row, const int* __restrict__ col,
            const float* __restrict__ b1, const float* __restrict__ W2,
            const float* __restrict__ b2, float* __restrict__ out)
{
    extern __shared__ char sm[];
    uint32_t smb = (uint32_t)__cvta_generic_to_shared(sm);
    int*   rs2 = (int*)(sm + SM_RS);
    int*   cs2 = (int*)(sm + SM_CS);
    float* b1s = (float*)(sm + SM_B1);
    float* w2s = (float*)(sm + SM_W2);
    float* b2s = (float*)(sm + SM_B2);
    float* opart = (float*)(sm + SM_OP);

    const int tid  = threadIdx.x;
    const int lane = tid & 31;
    const int w    = tid >> 5;
    const int wm   = w & 3, wn = w >> 2;
    const int m0   = wm * 32, n0 = wn * 32;

    if (tid < 128) b1s[tid] = b1[tid];
    if (tid < 512) w2s[tid] = W2[tid];
    if (tid < 4)   b2s[tid] = b2[tid];

    int nLocal = 0;
    for (int t = blockIdx.x; t < NT_EDGE; t += GRID_P) nLocal++;
    if (nLocal == 0) return;
    const int totalQ = nLocal * 5;

    for (int idx = tid; idx < 4608; idx += 512) {
        int b, n, fc;
        if (idx < 4096) { b = idx >> 10; n = (idx >> 3) & 127; fc = idx & 7; }
        else            { b = 4; n = (idx - 4096) >> 2; fc = (idx - 4096) & 3; }
        uint32_t dst = sw128((uint32_t)(n * 128 + fc * 16));
        cp16(smb + SM_BH + b * BBLK + dst, w1h + (size_t)n * KTOT + b * 64 + fc * 8);
    }
    asm volatile("cp.async.commit_group;");

    if (tid < 128) {
        int e = min(blockIdx.x * 128 + tid, EE - 1);
        rs2[tid] = row[e];
        cs2[tid] = col[e];
    }
    __syncthreads();

    auto fill = [&](int q) {
        int k = q / 5, c = q - k * 5;
        int ib = k & 1;
        uint32_t abase = smb + SM_AST + (q & (NSTG - 1)) * 16384;
        if (c < 4) {
#pragma unroll
            for (int it = 0; it < 2; it++) {
                int idx = tid + it * 512;
                int fr = idx >> 3, fc = idx & 7;
                int node = (c < 2) ? rs2[ib * 128 + fr] : cs2[ib * 128 + fr];
                int koff = ((c & 1) << 6) + fc * 8;
                cp16(abase + sw128((uint32_t)(fr * 128 + fc * 16)),
                     h16 + (size_t)node * HH + koff);
            }
        } else {
            int fr = tid >> 2, fc = tid & 3;
            int e0 = (blockIdx.x + k * GRID_P) * 128;
            int e = min(e0 + fr, EE - 1);
            cp16(abase + sw128((uint32_t)(fr * 128 + fc * 16)),
                 ea16 + (size_t)e * FE + fc * 8);
        }
        asm volatile("cp.async.commit_group;");
    };

    fill(0); fill(1); fill(2);

    const int gi   = lane & 7;
    const int gA_r = (lane >> 3) & 1;
    const int gA_c = lane >> 4;
    const int gB_r = lane >> 4;
    const int gB_c = (lane >> 3) & 1;

    float acc[2][4][4];

    for (int q = 0; q < totalQ; q++) {
        int k = q / 5, c = q - k * 5;

        asm volatile("cp.async.wait_group 2;" ::: "memory");
        __syncthreads();
        if (q + 3 < totalQ) fill(q + 3);

        if (c == 0) {
            if (k + 1 < nLocal && tid < 128) {
                int e = min((blockIdx.x + (k + 1) * GRID_P) * 128 + tid, EE - 1);
                rs2[((k + 1) & 1) * 128 + tid] = row[e];
                cs2[((k + 1) & 1) * 128 + tid] = col[e];
            }
#pragma unroll
            for (int i = 0; i < 2; i++)
#pragma unroll
                for (int j = 0; j < 4; j++)
#pragma unroll
                    for (int x = 0; x < 4; x++) acc[i][j][x] = 0.f;
        }

        uint32_t abase = smb + SM_AST + (q & (NSTG - 1)) * 16384;
        int nks = (c == 4) ? 2 : 4;
        for (int ks = 0; ks < nks; ks++) {
            uint32_t a[2][4];
#pragma unroll
            for (int mt = 0; mt < 2; mt++) {
                int r = m0 + mt * 16 + (gA_r << 3) + gi;
                ldsm_x4(a[mt], abase + sw128((uint32_t)(r * 128 + (ks * 2 + gA_c) * 16)));
            }
            uint32_t bh[4][2];
#pragma unroll
            for (int p = 0; p < 2; p++) {
                int n = n0 + (p << 4) + (gB_r << 3) + gi;
                uint32_t off = (uint32_t)(c * BBLK) + sw128((uint32_t)(n * 128 + (ks * 2 + gB_c) * 16));
                uint32_t t4[4];
                ldsm_x4(t4, smb + SM_BH + off);
                bh[2 * p][0] = t4[0]; bh[2 * p][1] = t4[1];
                bh[2 * p + 1][0] = t4[2]; bh[2 * p + 1][1] = t4[3];
            }
#pragma unroll
            for (int mt = 0; mt < 2; mt++)
#pragma unroll
                for (int nt = 0; nt < 4; nt++)
                    mma_f16(acc[mt][nt], a[mt], bh[nt][0], bh[nt][1]);
        }

        if (c == 4) {
            int e0 = (blockIdx.x + k * GRID_P) * 128;
            float p[4][4];
#pragma unroll
            for (int i = 0; i < 4; i++)
#pragma unroll
                for (int j = 0; j < 4; j++) p[i][j] = 0.f;

#pragma unroll
            for (int mt = 0; mt < 2; mt++)
#pragma unroll
                for (int hf = 0; hf < 2; hf++) {
                    int ri = mt * 2 + hf;
#pragma unroll
                    for (int nt = 0; nt < 4; nt++)
#pragma unroll
                        for (int e = 0; e < 2; e++) {
                            int colg = n0 + nt * 8 + (lane & 3) * 2 + e;
                            float h1 = fmaxf(acc[mt][nt][hf * 2 + e] + b1s[colg], 0.f);
#pragma unroll
                            for (int cc = 0; cc < 4; cc++)
                                p[ri][cc] += h1 * w2s[colg * 4 + cc];
                        }
                }
#pragma unroll
            for (int i = 0; i < 4; i++)
#pragma unroll
                for (int cc = 0; cc < 4; cc++) {
                    p[i][cc] += __shfl_xor_sync(0xffffffffu, p[i][cc], 1);
                    p[i][cc] += __shfl_xor_sync(0xffffffffu, p[i][cc], 2);
                }
            if ((lane & 3) == 0) {
#pragma unroll
                for (int mt = 0; mt < 2; mt++)
#pragma unroll
                    for (int hf = 0; hf < 2; hf++) {
                        int r = m0 + mt * 16 + (lane >> 2) + hf * 8;
#pragma unroll
                        for (int cc = 0; cc < 4; cc++)
                            opart[wn * 512 + r * 4 + cc] = p[mt * 2 + hf][cc];
                    }
            }
            __syncthreads();
            {
                int r = tid >> 2, cc = tid & 3;
                float s = opart[tid] + opart[512 + tid] + opart[1024 + tid]
                        + opart[1536 + tid] + b2s[cc];
                if (e0 + r < EE) out[(size_t)(e0 + r) * 4 + cc] = s;
            }
            __syncthreads();
        }
    }
}

// ---------------------------------------------------------------------------
extern "C" void kernel_launch(void* const* d_in, const int* in_sizes, int n_in,
                              void* d_out, int out_size)
{
    const float* x   = (const float*)d_in[0];
    const int*   ei  = (const int*)  d_in[1];
    const float* ea  = (const float*)d_in[2];
    const float* We  = (const float*)d_in[3];
    const float* be  = (const float*)d_in[4];
    const float* Wc1 = (const float*)d_in[5];
    const float* bc1 = (const float*)d_in[6];
    const float* Wc2 = (const float*)d_in[7];
    const float* bc2 = (const float*)d_in[8];
    const float* Wn1 = (const float*)d_in[9];
    const float* bn1 = (const float*)d_in[10];
    const float* Wn2 = (const float*)d_in[11];
    const float* bn2 = (const float*)d_in[12];
    const float* We1 = (const float*)d_in[13];
    const float* be1 = (const float*)d_in[14];
    const float* We2 = (const float*)d_in[15];
    const float* be2 = (const float*)d_in[16];

    const int* row = ei;
    const int* col = ei + EE;

    float* out_node = (float*)d_out;
    float* out_edge = out_node + (size_t)NN * CN;

    float *pxw, *pacc, *pdinv;
    int* pdeg;
    __half *pxh, *pxl, *phh, *phl, *pth, *ptl, *pea16, *pw1h;
    __half *wWeH, *wWeL, *wC1H, *wC1L, *wC2H, *wC2L, *wN1H, *wN1L, *wN2H, *wN2L;
    cudaGetSymbolAddress((void**)&pxw,   g_xw);
    cudaGetSymbolAddress((void**)&pacc,  g_acc);
    cudaGetSymbolAddress((void**)&pdinv, g_dinv);
    cudaGetSymbolAddress((void**)&pdeg,  g_deg);
    cudaGetSymbolAddress((void**)&pxh,   g_xh);
    cudaGetSymbolAddress((void**)&pxl,   g_xl);
    cudaGetSymbolAddress((void**)&phh,   g_hh);
    cudaGetSymbolAddress((void**)&phl,   g_hl);
    cudaGetSymbolAddress((void**)&pth,   g_th);
    cudaGetSymbolAddress((void**)&ptl,   g_tl);
    cudaGetSymbolAddress((void**)&pea16, g_ea16);
    cudaGetSymbolAddress((void**)&pw1h,  g_w1h);
    cudaGetSymbolAddress((void**)&wWeH,  g_wWe_h);
    cudaGetSymbolAddress((void**)&wWeL,  g_wWe_l);
    cudaGetSymbolAddress((void**)&wC1H,  g_wC1_h);
    cudaGetSymbolAddress((void**)&wC1L,  g_wC1_l);
    cudaGetSymbolAddress((void**)&wC2H,  g_wC2_h);
    cudaGetSymbolAddress((void**)&wC2L,  g_wC2_l);
    cudaGetSymbolAddress((void**)&wN1H,  g_wN1_h);
    cudaGetSymbolAddress((void**)&wN1L,  g_wN1_l);
    cudaGetSymbolAddress((void**)&wN2H,  g_wN2_h);
    cudaGetSymbolAddress((void**)&wN2L,  g_wN2_l);

    static bool attr_set = false;
    if (!attr_set) {
        cudaFuncSetAttribute(k_edge, cudaFuncAttributeMaxDynamicSharedMemorySize, SM_END);
        cudaFuncSetAttribute(k_mm<1,0>, cudaFuncAttributeMaxDynamicSharedMemorySize, MM_SM_END);
        cudaFuncSetAttribute(k_mm<2,1>, cudaFuncAttributeMaxDynamicSharedMemorySize, MM_SM_END);
        cudaFuncSetAttribute(k_mm<2,2>, cudaFuncAttributeMaxDynamicSharedMemorySize, MM_SM_END);
        cudaFuncSetAttribute(k_mm<1,3>, cudaFuncAttributeMaxDynamicSharedMemorySize, MM_SM_END);
        attr_set = true;
    }

    const int T = 256;

    // degrees + norm
    k_deg_init<<<(NN + T - 1) / T, T>>>(pdeg);
    k_deg_edges<<<(EE + T - 1) / T, T>>>(col, pdeg);
    k_dinv<<<(NN + T - 1) / T, T>>>(pdeg, pdinv);

    // conversions / splits
    {
        size_t n8 = (size_t)EE * FE / 8;
        k_tof16_v<<<(int)((n8 + T - 1) / T), T>>>((const float4*)ea, (uint4*)pea16, n8);
    }
    k_w1t16<<<(HH * KTOT + T - 1) / T, T>>>(We1, pw1h);
    k_splitA<<<(int)(((size_t)NN * FN + T - 1) / T), T>>>(x, pxh, pxl, (size_t)NN * FN);
    k_splitWt<<<(128 * 64 + T - 1) / T, T>>>(We, wWeH, wWeL, 64, 128);
    k_splitWt<<<(128 * 128 + T - 1) / T, T>>>(Wc1, wC1H, wC1L, 128, 128);
    k_splitWt<<<(128 * 128 + T - 1) / T, T>>>(Wc2, wC2H, wC2L, 128, 128);
    k_splitWt<<<(128 * 128 + T - 1) / T, T>>>(Wn1, wN1H, wN1L, 128, 64);
    k_splitWt<<<(128 * 64 + T - 1) / T, T>>>(Wn2, wN2H, wN2L, 64, CN);

    // embed: h = relu(x @ We + be)  -> hh/hl
    k_mm<1,0><<<GRID_P, 512, MM_SM_END>>>(pxh, pxl, wWeH, wWeL, be, nullptr,
                                          nullptr, nullptr, phh, phl, NN, 128);
    // conv1 GEMM -> xw + selfloop acc
    k_mm<2,1><<<GRID_P, 512, MM_SM_END>>>(phh, phl, wC1H, wC1L, nullptr, pdinv,
                                          pxw, pacc, nullptr, nullptr, NN, 128);
    k_scatter<<<(int)(((size_t)EE * 32 + T - 1) / T), T>>>(pxw, row, col, pdinv, pacc);
    k_bias_relu_split<<<(int)(((size_t)NN * HH + T - 1) / T), T>>>(pacc, bc1, phh, phl);

    // conv2
    k_mm<2,1><<<GRID_P, 512, MM_SM_END>>>(phh, phl, wC2H, wC2L, nullptr, pdinv,
                                          pxw, pacc, nullptr, nullptr, NN, 128);
    k_scatter<<<(int)(((size_t)EE * 32 + T - 1) / T), T>>>(pxw, row, col, pdinv, pacc);
    k_bias_relu_split<<<(int)(((size_t)NN * HH + T - 1) / T), T>>>(pacc, bc2, phh, phl);

    // node head
    k_mm<2,2><<<GRID_P, 512, MM_SM_END>>>(phh, phl, wN1H, wN1L, bn1, nullptr,
                                          nullptr, nullptr, pth, ptl, NN, 64);
    k_mm<1,3><<<GRID_P, 512, MM_SM_END>>>(pth, ptl, wN2H, wN2L, bn2, nullptr,
                                          out_node, nullptr, nullptr, nullptr, NN, CN);

    // edge MLP (persistent, resident W1t, single-pass fp16 mma)
    k_edge<<<GRID_P, 512, SM_END>>>(phh, pea16, pw1h, row, col,
                                    be1, We2, be2, out_edge);
}

// round 8
// speedup vs baseline: 3.3437x; 1.0481x over previous
#include <cuda_runtime.h>
#include <cuda_fp16.h>
#include <cstdint>

#define NN 100000
#define EE 1000000
#define HH 128
#define FN 64
#define FE 32
#define CN 12
#define CE 4
#define KTOT 288
#define NT_EDGE ((EE + 127) / 128)   // 7813
#define GRID_P 148

// ---------------------------------------------------------------------------
// Scratch (device globals — no cudaMalloc allowed)
// ---------------------------------------------------------------------------
__device__ float g_xw [(size_t)NN * HH];
__device__ float g_acc[(size_t)NN * HH];
__device__ float g_dinv[NN];
__device__ int   g_deg [NN];

__device__ __align__(16) __half g_xh [(size_t)NN * FN];
__device__ __align__(16) __half g_xl [(size_t)NN * FN];
__device__ __align__(16) __half g_hh [(size_t)NN * HH];
__device__ __align__(16) __half g_hl [(size_t)NN * HH];
__device__ __align__(16) __half g_th [(size_t)NN * 64];
__device__ __align__(16) __half g_tl [(size_t)NN * 64];
__device__ __align__(16) __half g_ea16[(size_t)EE * FE];
__device__ __align__(16) __half g_w1h [HH * KTOT];

// node-path weight transposes (hi/lo), N padded to 128 rows
__device__ __align__(16) __half g_wWe_h[128 * 64],  g_wWe_l[128 * 64];
__device__ __align__(16) __half g_wC1_h[128 * 128], g_wC1_l[128 * 128];
__device__ __align__(16) __half g_wC2_h[128 * 128], g_wC2_l[128 * 128];
__device__ __align__(16) __half g_wN1_h[128 * 128], g_wN1_l[128 * 128];
__device__ __align__(16) __half g_wN2_h[128 * 64],  g_wN2_l[128 * 64];

// ---------------------------------------------------------------------------
// Degree / normalization
// ---------------------------------------------------------------------------
__global__ void k_deg_init(int* __restrict__ deg) {
    int i = blockIdx.x * blockDim.x + threadIdx.x;
    if (i < NN) deg[i] = 1;
}
__global__ void k_deg_edges(const int* __restrict__ col, int* __restrict__ deg) {
    int e = blockIdx.x * blockDim.x + threadIdx.x;
    if (e < EE) atomicAdd(&deg[col[e]], 1);
}
__global__ void k_dinv(const int* __restrict__ deg, float* __restrict__ dinv) {
    int i = blockIdx.x * blockDim.x + threadIdx.x;
    if (i < NN) dinv[i] = rsqrtf((float)deg[i]);
}

// ---------------------------------------------------------------------------
// splits
// ---------------------------------------------------------------------------
__global__ void k_splitA(const float* __restrict__ in, __half* __restrict__ hi,
                         __half* __restrict__ lo, size_t n)
{
    size_t i = (size_t)blockIdx.x * blockDim.x + threadIdx.x;
    if (i < n) {
        float x = in[i];
        __half h = __float2half_rn(x);
        hi[i] = h;
        lo[i] = __float2half_rn(x - __half2float(h));
    }
}

// W [K][Nn] -> Wt hi/lo [128][K], rows n>=Nn zeroed
__global__ void k_splitWt(const float* __restrict__ W, __half* __restrict__ hi,
                          __half* __restrict__ lo, int K, int Nn)
{
    int i = blockIdx.x * blockDim.x + threadIdx.x;
    if (i < 128 * K) {
        int n = i / K, k = i % K;
        float x = (n < Nn) ? W[(size_t)k * Nn + n] : 0.f;
        __half h = __float2half_rn(x);
        hi[i] = h;
        lo[i] = __float2half_rn(x - __half2float(h));
    }
}

// vectorized fp32 -> fp16, 8 elements / thread
__global__ void k_tof16_v(const float4* __restrict__ in, uint4* __restrict__ o, size_t n8)
{
    size_t i = (size_t)blockIdx.x * blockDim.x + threadIdx.x;
    if (i >= n8) return;
    float4 a = in[i * 2];
    float4 b = in[i * 2 + 1];
    __half2 h[4];
    h[0] = __floats2half2_rn(a.x, a.y);
    h[1] = __floats2half2_rn(a.z, a.w);
    h[2] = __floats2half2_rn(b.x, b.y);
    h[3] = __floats2half2_rn(b.z, b.w);
    o[i] = *reinterpret_cast<const uint4*>(h);
}

// W1 [K=288][N=128] -> W1t [N=128][K=288] fp16 (edge MLP)
__global__ void k_w1t16(const float* __restrict__ W1, __half* __restrict__ o)
{
    int i = blockIdx.x * blockDim.x + threadIdx.x;
    if (i < HH * KTOT) {
        int n = i / KTOT, k = i % KTOT;
        o[i] = __float2half_rn(W1[(size_t)k * HH + n]);
    }
}

// ---------------------------------------------------------------------------
// GCN aggregation
// ---------------------------------------------------------------------------
__global__ __launch_bounds__(256)
void k_scatter(const float* __restrict__ xw, const int* __restrict__ row,
               const int* __restrict__ col, const float* __restrict__ dinv,
               float* __restrict__ acc)
{
    int idx = blockIdx.x * blockDim.x + threadIdx.x;
    int e = idx >> 5;
    int lane = idx & 31;
    if (e >= EE) return;
    int s = __ldg(&row[e]);
    int t = __ldg(&col[e]);
    float c = dinv[s] * dinv[t];
    float4 v = ((const float4*)(xw + (size_t)s * HH))[lane];
    float* dst = acc + (size_t)t * HH + lane * 4;
    asm volatile("red.global.add.v4.f32 [%0], {%1, %2, %3, %4};"
                 :: "l"(dst), "f"(v.x * c), "f"(v.y * c), "f"(v.z * c), "f"(v.w * c)
                 : "memory");
}

// acc + bias -> relu -> hi/lo fp16 split
__global__ void k_bias_relu_split(const float* __restrict__ acc, const float* __restrict__ b,
                                  __half* __restrict__ hh, __half* __restrict__ hl)
{
    size_t i = (size_t)blockIdx.x * blockDim.x + threadIdx.x;
    if (i < (size_t)NN * HH) {
        float v = fmaxf(acc[i] + b[i & (HH - 1)], 0.f);
        __half h = __float2half_rn(v);
        hh[i] = h;
        hl[i] = __float2half_rn(v - __half2float(h));
    }
}

// ---------------------------------------------------------------------------
// mma helpers
// ---------------------------------------------------------------------------
__device__ __forceinline__ uint32_t sw128(uint32_t byte_off) {
    return byte_off ^ ((byte_off >> 3) & 0x70);
}
__device__ __forceinline__ void ldsm_x4(uint32_t (&r)[4], uint32_t addr) {
    asm volatile("ldmatrix.sync.aligned.m8n8.x4.shared.b16 {%0,%1,%2,%3}, [%4];"
                 : "=r"(r[0]), "=r"(r[1]), "=r"(r[2]), "=r"(r[3]) : "r"(addr));
}
__device__ __forceinline__ void mma_f16(float (&d)[4], const uint32_t (&a)[4],
                                        uint32_t b0, uint32_t b1) {
    asm volatile("mma.sync.aligned.m16n8k16.row.col.f32.f16.f16.f32 "
                 "{%0,%1,%2,%3},{%4,%5,%6,%7},{%8,%9},{%0,%1,%2,%3};"
                 : "+f"(d[0]), "+f"(d[1]), "+f"(d[2]), "+f"(d[3])
                 : "r"(a[0]), "r"(a[1]), "r"(a[2]), "r"(a[3]), "r"(b0), "r"(b1));
}
__device__ __forceinline__ void cp16(uint32_t saddr, const void* gaddr) {
    asm volatile("cp.async.cg.shared.global [%0], [%1], 16;" :: "r"(saddr), "l"(gaddr));
}
__device__ __forceinline__ void bulk_ld(uint32_t dst, const void* src, uint32_t bytes,
                                        uint32_t mbar) {
    asm volatile("cp.async.bulk.shared::cluster.global.mbarrier::complete_tx::bytes "
                 "[%0], [%1], %2, [%3];"
                 :: "r"(dst), "l"(src), "r"(bytes), "r"(mbar) : "memory");
}
__device__ __forceinline__ void mbar_init(uint32_t mbar, uint32_t cnt) {
    asm volatile("mbarrier.init.shared.b64 [%0], %1;" :: "r"(mbar), "r"(cnt) : "memory");
}
__device__ __forceinline__ void mbar_expect(uint32_t mbar, uint32_t bytes) {
    asm volatile("mbarrier.arrive.expect_tx.shared.b64 _, [%0], %1;"
                 :: "r"(mbar), "r"(bytes) : "memory");
}
__device__ __forceinline__ void mbar_wait(uint32_t mbar, uint32_t parity) {
    uint32_t done = 0;
    while (!done) {
        asm volatile("{\n\t.reg .pred p;\n\t"
                     "mbarrier.try_wait.parity.shared::cta.b64 p, [%1], %2;\n\t"
                     "selp.b32 %0, 1, 0, p;\n\t}"
                     : "=r"(done) : "r"(mbar), "r"(parity) : "memory");
    }
}

// ---------------------------------------------------------------------------
// Unified node-path GEMM: persistent, split-fp16 3-pass (Ah*Bh + Ah*Bl + Al*Bh).
// ---------------------------------------------------------------------------
#define MM_SM_B   0
#define MM_SM_A   65536
#define MM_SM_BIAS (65536 + 3 * 32768)
#define MM_SM_END (MM_SM_BIAS + 512)

template<int KCH, int EPI>
__global__ __launch_bounds__(512, 1)
void k_mm(const __half* __restrict__ Ah, const __half* __restrict__ Al,
          const __half* __restrict__ Bth, const __half* __restrict__ Btl,
          const float* __restrict__ bias, const float* __restrict__ dinv,
          float* __restrict__ outF, float* __restrict__ outAcc,
          __half* __restrict__ outH, __half* __restrict__ outL,
          int M, int Nn)
{
    constexpr int K = KCH * 64;
    extern __shared__ char sm[];
    uint32_t smb = (uint32_t)__cvta_generic_to_shared(sm);
    float* b1s = (float*)(sm + MM_SM_BIAS);

    const int tid  = threadIdx.x;
    const int lane = tid & 31;
    const int w    = tid >> 5;
    const int wm   = w & 3, wn = w >> 2;
    const int m0   = wm * 32, n0 = wn * 32;

    const int NT = (M + 127) / 128;
    int nLocal = 0;
    for (int t = blockIdx.x; t < NT; t += GRID_P) nLocal++;
    if (nLocal == 0) return;
    const int totalQ = nLocal * KCH;

    for (int idx = tid; idx < 2 * KCH * 1024; idx += 512) {
        int b = idx >> 10, rem = idx & 1023;
        int n = rem >> 3, fc = rem & 7;
        int cb = b >> 1, hl = b & 1;
        const __half* src = (hl ? Btl : Bth) + (size_t)n * K + cb * 64 + fc * 8;
        cp16(smb + MM_SM_B + b * 16384 + sw128((uint32_t)(n * 128 + fc * 16)), src);
    }
    asm volatile("cp.async.commit_group;");

    if (tid < 128) b1s[tid] = (bias && tid < Nn) ? bias[tid] : 0.f;
    __syncthreads();

    auto fill = [&](int q) {
        int k = q / KCH, c = q - k * KCH;
        int m0g = (blockIdx.x + k * GRID_P) * 128;
        uint32_t abase = smb + MM_SM_A + (q % 3) * 32768;
#pragma unroll
        for (int it = 0; it < 2; it++) {
            int idx = tid + it * 512;
            int fr = idx >> 3, fc = idx & 7;
            int gm = min(m0g + fr, M - 1);
            size_t so = (size_t)gm * K + c * 64 + fc * 8;
            uint32_t d = sw128((uint32_t)(fr * 128 + fc * 16));
            cp16(abase + d, Ah + so);
            cp16(abase + 16384 + d, Al + so);
        }
        asm volatile("cp.async.commit_group;");
    };

    fill(0);
    if (totalQ > 1) fill(1);

    const int gi   = lane & 7;
    const int gA_r = (lane >> 3) & 1;
    const int gA_c = lane >> 4;
    const int gB_r = lane >> 4;
    const int gB_c = (lane >> 3) & 1;

    float acc[2][4][4];

    for (int q = 0; q < totalQ; q++) {
        int k = q / KCH, c = q - k * KCH;

        if (q + 1 < totalQ) { asm volatile("cp.async.wait_group 1;" ::: "memory"); }
        else                { asm volatile("cp.async.wait_group 0;" ::: "memory"); }
        __syncthreads();
        if (q + 2 < totalQ) fill(q + 2);

        if (c == 0) {
#pragma unroll
            for (int i = 0; i < 2; i++)
#pragma unroll
                for (int j = 0; j < 4; j++)
#pragma unroll
                    for (int x = 0; x < 4; x++) acc[i][j][x] = 0.f;
        }

        uint32_t abase = smb + MM_SM_A + (q % 3) * 32768;
        uint32_t bhB = smb + MM_SM_B + (c * 2) * 16384;
        uint32_t blB = bhB + 16384;
#pragma unroll
        for (int ks = 0; ks < 4; ks++) {
            uint32_t ah[2][4], al[2][4];
#pragma unroll
            for (int mt = 0; mt < 2; mt++) {
                int r = m0 + mt * 16 + (gA_r << 3) + gi;
                uint32_t off = sw128((uint32_t)(r * 128 + (ks * 2 + gA_c) * 16));
                ldsm_x4(ah[mt], abase + off);
                ldsm_x4(al[mt], abase + 16384 + off);
            }
            uint32_t bh[4][2], bl[4][2];
#pragma unroll
            for (int p = 0; p < 2; p++) {
                int n = n0 + (p << 4) + (gB_r << 3) + gi;
                uint32_t off = sw128((uint32_t)(n * 128 + (ks * 2 + gB_c) * 16));
                uint32_t t4[4];
                ldsm_x4(t4, bhB + off);
                bh[2 * p][0] = t4[0]; bh[2 * p][1] = t4[1];
                bh[2 * p + 1][0] = t4[2]; bh[2 * p + 1][1] = t4[3];
                ldsm_x4(t4, blB + off);
                bl[2 * p][0] = t4[0]; bl[2 * p][1] = t4[1];
                bl[2 * p + 1][0] = t4[2]; bl[2 * p + 1][1] = t4[3];
            }
#pragma unroll
            for (int mt = 0; mt < 2; mt++)
#pragma unroll
                for (int nt = 0; nt < 4; nt++) {
                    mma_f16(acc[mt][nt], ah[mt], bh[nt][0], bh[nt][1]);
                    mma_f16(acc[mt][nt], ah[mt], bl[nt][0], bl[nt][1]);
                    mma_f16(acc[mt][nt], al[mt], bh[nt][0], bh[nt][1]);
                }
        }

        if (c == KCH - 1) {
            int m0g = (blockIdx.x + k * GRID_P) * 128;
#pragma unroll
            for (int mt = 0; mt < 2; mt++)
#pragma unroll
                for (int hf = 0; hf < 2; hf++) {
                    int gm = m0g + m0 + mt * 16 + (lane >> 2) + hf * 8;
                    if (gm >= M) continue;
                    float d2 = 0.f;
                    if (EPI == 1) { float d = dinv[gm]; d2 = d * d; }
#pragma unroll
                    for (int nt = 0; nt < 4; nt++)
#pragma unroll
                        for (int e = 0; e < 2; e++) {
                            int n = n0 + nt * 8 + (lane & 3) * 2 + e;
                            float v = acc[mt][nt][hf * 2 + e];
                            if (EPI == 0) {
                                v = fmaxf(v + b1s[n], 0.f);
                                __half h = __float2half_rn(v);
                                outH[(size_t)gm * 128 + n] = h;
                                outL[(size_t)gm * 128 + n] =
                                    __float2half_rn(v - __half2float(h));
                            } else if (EPI == 1) {
                                outF[(size_t)gm * 128 + n] = v;
                                outAcc[(size_t)gm * 128 + n] = v * d2;
                            } else if (EPI == 2) {
                                if (n < 64) {
                                    v = fmaxf(v + b1s[n], 0.f);
                                    __half h = __float2half_rn(v);
                                    outH[(size_t)gm * 64 + n] = h;
                                    outL[(size_t)gm * 64 + n] =
                                        __float2half_rn(v - __half2float(h));
                                }
                            } else {
                                if (n < CN) outF[(size_t)gm * CN + n] = v + b1s[n];
                            }
                        }
                }
        }
    }
}

// ---------------------------------------------------------------------------
// Edge MLP v2: persistent CTAs, W1t fp16 resident, gathered rows via
// cp.async.bulk (256B/row) into stride-272 unswizzled stages, mbarrier
// completion. 2 full-tile stages (src+tgt) + single-buffered ea tile.
// ---------------------------------------------------------------------------
#define STG_SZ   69632                  // src (128x272) + tgt (128x272)
#define ESM_B0   0                      // W1t blocks 0-3, sw128, 4x16384
#define ESM_B4   65536                  // W1t block 4 compact, 128x64B
#define ESM_ST   73728                  // 2 stages x 69632
#define ESM_EA   212992                 // ea tile, 128x64B
#define ESM_B1   221184                 // b1, 128 f
#define ESM_W2   221696                 // W2, 512 f
#define ESM_B2   223744                 // b2, 4 f
#define ESM_OP   223760                 // out partials [4][128][4] f
#define ESM_MBAR 231952                 // 3 mbarriers
#define ESM_END  231976

__global__ __launch_bounds__(512, 1)
void k_edge(const __half* __restrict__ h16, const __half* __restrict__ ea16,
            const __half* __restrict__ w1h,
            const int* __restrict__ row, const int* __restrict__ col,
            const float* __restrict__ b1, const float* __restrict__ W2,
            const float* __restrict__ b2, float* __restrict__ out)
{
    extern __shared__ char sm[];
    uint32_t smb = (uint32_t)__cvta_generic_to_shared(sm);
    float* b1s = (float*)(sm + ESM_B1);
    float* w2s = (float*)(sm + ESM_W2);
    float* b2s = (float*)(sm + ESM_B2);
    float* opart = (float*)(sm + ESM_OP);
    const uint32_t mb_st0 = smb + ESM_MBAR;
    const uint32_t mb_st1 = smb + ESM_MBAR + 8;
    const uint32_t mb_ea  = smb + ESM_MBAR + 16;

    const int tid  = threadIdx.x;
    const int lane = tid & 31;
    const int w    = tid >> 5;
    const int wm   = w & 3, wn = w >> 2;
    const int m0   = wm * 32, n0 = wn * 32;

    if (tid < 128) b1s[tid] = b1[tid];
    if (tid < 512) w2s[tid] = W2[tid];
    if (tid < 4)   b2s[tid] = b2[tid];
    if (tid == 0) { mbar_init(mb_st0, 1); mbar_init(mb_st1, 1); mbar_init(mb_ea, 1); }

    int nLocal = 0;
    for (int t = blockIdx.x; t < NT_EDGE; t += GRID_P) nLocal++;
    if (nLocal == 0) return;

    // resident B: blocks 0-3 sw128 (16KB each), block 4 compact (8KB, 64B rows)
    for (int idx = tid; idx < 4608; idx += 512) {
        uint32_t dst; const __half* src;
        if (idx < 4096) {
            int b = idx >> 10, n = (idx >> 3) & 127, fc = idx & 7;
            dst = ESM_B0 + b * 16384 + sw128((uint32_t)(n * 128 + fc * 16));
            src = w1h + (size_t)n * KTOT + b * 64 + fc * 8;
        } else {
            int i2 = idx - 4096, n = i2 >> 2, fc = i2 & 3;
            dst = ESM_B4 + n * 64 + fc * 16;
            src = w1h + (size_t)n * KTOT + 256 + fc * 8;
        }
        cp16(smb + dst, src);
    }
    asm volatile("cp.async.commit_group;");
    __syncthreads();   // mbarrier init + tables visible before bulk fills

    // fill src+tgt rows of tile k into stage k&1 (65536 tx bytes)
    auto fill_st = [&](int k) {
        uint32_t st = smb + ESM_ST + (k & 1) * STG_SZ;
        uint32_t bar = (k & 1) ? mb_st1 : mb_st0;
        int e0 = (blockIdx.x + k * GRID_P) * 128;
        if (tid == 0) mbar_expect(bar, 65536);
        if (tid < 128) {
            int node = __ldg(&row[min(e0 + tid, EE - 1)]);
            bulk_ld(st + tid * 272, h16 + (size_t)node * HH, 256, bar);
        } else if (tid < 256) {
            int t2 = tid - 128;
            int node = __ldg(&col[min(e0 + t2, EE - 1)]);
            bulk_ld(st + 34816 + t2 * 272, h16 + (size_t)node * HH, 256, bar);
        }
    };
    // fill ea tile of tile k (single buffer; clamp last tile)
    auto fill_ea = [&](int k) {
        if (tid == 256) {
            int e0 = (blockIdx.x + k * GRID_P) * 128;
            int valid = min(128, EE - e0);
            uint32_t bytes = (uint32_t)valid * 64;
            mbar_expect(mb_ea, bytes);
            bulk_ld(smb + ESM_EA, ea16 + (size_t)e0 * FE, bytes, mb_ea);
        }
    };

    fill_st(0);
    if (nLocal > 1) fill_st(1);
    fill_ea(0);

    asm volatile("cp.async.wait_group 0;" ::: "memory");
    __syncthreads();   // B resident complete for all threads

    const int gi   = lane & 7;
    const int gA_r = (lane >> 3) & 1;
    const int gA_c = lane >> 4;
    const int gB_r = lane >> 4;
    const int gB_c = (lane >> 3) & 1;

    for (int k = 0; k < nLocal; k++) {
        const int kb = k & 1;
        const uint32_t st = smb + ESM_ST + kb * STG_SZ;
        const int e0 = (blockIdx.x + k * GRID_P) * 128;

        mbar_wait(kb ? mb_st1 : mb_st0, (k >> 1) & 1);

        float acc[2][4][4];
#pragma unroll
        for (int i = 0; i < 2; i++)
#pragma unroll
            for (int j = 0; j < 4; j++)
#pragma unroll
                for (int x = 0; x < 4; x++) acc[i][j][x] = 0.f;

        // chunks 0-3: h[src] / h[tgt], 64 k-cols each
#pragma unroll
        for (int c = 0; c < 4; c++) {
            uint32_t abase = st + ((c >= 2) ? 34816u : 0u) + (uint32_t)((c & 1) * 128);
            uint32_t bbase = smb + ESM_B0 + c * 16384;
#pragma unroll
            for (int ks = 0; ks < 4; ks++) {
                uint32_t a[2][4];
#pragma unroll
                for (int mt = 0; mt < 2; mt++) {
                    int r = m0 + mt * 16 + (gA_r << 3) + gi;
                    ldsm_x4(a[mt], abase + (uint32_t)(r * 272 + (ks * 2 + gA_c) * 16));
                }
                uint32_t bh[4][2];
#pragma unroll
                for (int p = 0; p < 2; p++) {
                    int n = n0 + (p << 4) + (gB_r << 3) + gi;
                    uint32_t t4[4];
                    ldsm_x4(t4, bbase + sw128((uint32_t)(n * 128 + (ks * 2 + gB_c) * 16)));
                    bh[2 * p][0] = t4[0]; bh[2 * p][1] = t4[1];
                    bh[2 * p + 1][0] = t4[2]; bh[2 * p + 1][1] = t4[3];
                }
#pragma unroll
                for (int mt = 0; mt < 2; mt++)
#pragma unroll
                    for (int nt = 0; nt < 4; nt++)
                        mma_f16(acc[mt][nt], a[mt], bh[nt][0], bh[nt][1]);
            }
        }

        // chunk 4: edge_attr (32 k-cols)
        mbar_wait(mb_ea, k & 1);
#pragma unroll
        for (int ks = 0; ks < 2; ks++) {
            uint32_t a[2][4];
#pragma unroll
            for (int mt = 0; mt < 2; mt++) {
                int r = m0 + mt * 16 + (gA_r << 3) + gi;
                ldsm_x4(a[mt], smb + ESM_EA + (uint32_t)(r * 64 + (ks * 2 + gA_c) * 16));
            }
            uint32_t bh[4][2];
#pragma unroll
            for (int p = 0; p < 2; p++) {
                int n = n0 + (p << 4) + (gB_r << 3) + gi;
                uint32_t t4[4];
                ldsm_x4(t4, smb + ESM_B4 + (uint32_t)(n * 64 + (ks * 2 + gB_c) * 16));
                bh[2 * p][0] = t4[0]; bh[2 * p][1] = t4[1];
                bh[2 * p + 1][0] = t4[2]; bh[2 * p + 1][1] = t4[3];
            }
#pragma unroll
            for (int mt = 0; mt < 2; mt++)
#pragma unroll
                for (int nt = 0; nt < 4; nt++)
                    mma_f16(acc[mt][nt], a[mt], bh[nt][0], bh[nt][1]);
        }

        // ----- epilogue: bias+relu on fragments, 128x4 GEMM, reduce -----
        {
            float p[4][4];
#pragma unroll
            for (int i = 0; i < 4; i++)
#pragma unroll
                for (int j = 0; j < 4; j++) p[i][j] = 0.f;

#pragma unroll
            for (int mt = 0; mt < 2; mt++)
#pragma unroll
                for (int hf = 0; hf < 2; hf++) {
                    int ri = mt * 2 + hf;
#pragma unroll
                    for (int nt = 0; nt < 4; nt++)
#pragma unroll
                        for (int e = 0; e < 2; e++) {
                            int colg = n0 + nt * 8 + (lane & 3) * 2 + e;
                            float h1 = fmaxf(acc[mt][nt][hf * 2 + e] + b1s[colg], 0.f);
#pragma unroll
                            for (int cc = 0; cc < 4; cc++)
                                p[ri][cc] += h1 * w2s[colg * 4 + cc];
                        }
                }
#pragma unroll
            for (int i = 0; i < 4; i++)
#pragma unroll
                for (int cc = 0; cc < 4; cc++) {
                    p[i][cc] += __shfl_xor_sync(0xffffffffu, p[i][cc], 1);
                    p[i][cc] += __shfl_xor_sync(0xffffffffu, p[i][cc], 2);
                }
            if ((lane & 3) == 0) {
#pragma unroll
                for (int mt = 0; mt < 2; mt++)
#pragma unroll
                    for (int hf = 0; hf < 2; hf++) {
                        int r = m0 + mt * 16 + (lane >> 2) + hf * 8;
#pragma unroll
                        for (int cc = 0; cc < 4; cc++)
                            opart[wn * 512 + r * 4 + cc] = p[mt * 2 + hf][cc];
                    }
            }
            __syncthreads();
            {
                int r = tid >> 2, cc = tid & 3;
                float s = opart[tid] + opart[512 + tid] + opart[1024 + tid]
                        + opart[1536 + tid] + b2s[cc];
                if (e0 + r < EE) out[(size_t)(e0 + r) * 4 + cc] = s;
            }
            __syncthreads();   // all threads done with stage kb, ea, opart
        }

        // issue next fills (stage kb is free; ea consumed)
        if (k + 2 < nLocal) fill_st(k + 2);
        if (k + 1 < nLocal) fill_ea(k + 1);
    }
}

// ---------------------------------------------------------------------------
extern "C" void kernel_launch(void* const* d_in, const int* in_sizes, int n_in,
                              void* d_out, int out_size)
{
    const float* x   = (const float*)d_in[0];
    const int*   ei  = (const int*)  d_in[1];
    const float* ea  = (const float*)d_in[2];
    const float* We  = (const float*)d_in[3];
    const float* be  = (const float*)d_in[4];
    const float* Wc1 = (const float*)d_in[5];
    const float* bc1 = (const float*)d_in[6];
    const float* Wc2 = (const float*)d_in[7];
    const float* bc2 = (const float*)d_in[8];
    const float* Wn1 = (const float*)d_in[9];
    const float* bn1 = (const float*)d_in[10];
    const float* Wn2 = (const float*)d_in[11];
    const float* bn2 = (const float*)d_in[12];
    const float* We1 = (const float*)d_in[13];
    const float* be1 = (const float*)d_in[14];
    const float* We2 = (const float*)d_in[15];
    const float* be2 = (const float*)d_in[16];

    const int* row = ei;
    const int* col = ei + EE;

    float* out_node = (float*)d_out;
    float* out_edge = out_node + (size_t)NN * CN;

    float *pxw, *pacc, *pdinv;
    int* pdeg;
    __half *pxh, *pxl, *phh, *phl, *pth, *ptl, *pea16, *pw1h;
    __half *wWeH, *wWeL, *wC1H, *wC1L, *wC2H, *wC2L, *wN1H, *wN1L, *wN2H, *wN2L;
    cudaGetSymbolAddress((void**)&pxw,   g_xw);
    cudaGetSymbolAddress((void**)&pacc,  g_acc);
    cudaGetSymbolAddress((void**)&pdinv, g_dinv);
    cudaGetSymbolAddress((void**)&pdeg,  g_deg);
    cudaGetSymbolAddress((void**)&pxh,   g_xh);
    cudaGetSymbolAddress((void**)&pxl,   g_xl);
    cudaGetSymbolAddress((void**)&phh,   g_hh);
    cudaGetSymbolAddress((void**)&phl,   g_hl);
    cudaGetSymbolAddress((void**)&pth,   g_th);
    cudaGetSymbolAddress((void**)&ptl,   g_tl);
    cudaGetSymbolAddress((void**)&pea16, g_ea16);
    cudaGetSymbolAddress((void**)&pw1h,  g_w1h);
    cudaGetSymbolAddress((void**)&wWeH,  g_wWe_h);
    cudaGetSymbolAddress((void**)&wWeL,  g_wWe_l);
    cudaGetSymbolAddress((void**)&wC1H,  g_wC1_h);
    cudaGetSymbolAddress((void**)&wC1L,  g_wC1_l);
    cudaGetSymbolAddress((void**)&wC2H,  g_wC2_h);
    cudaGetSymbolAddress((void**)&wC2L,  g_wC2_l);
    cudaGetSymbolAddress((void**)&wN1H,  g_wN1_h);
    cudaGetSymbolAddress((void**)&wN1L,  g_wN1_l);
    cudaGetSymbolAddress((void**)&wN2H,  g_wN2_h);
    cudaGetSymbolAddress((void**)&wN2L,  g_wN2_l);

    static bool attr_set = false;
    if (!attr_set) {
        cudaFuncSetAttribute(k_edge, cudaFuncAttributeMaxDynamicSharedMemorySize, ESM_END);
        cudaFuncSetAttribute(k_mm<1,0>, cudaFuncAttributeMaxDynamicSharedMemorySize, MM_SM_END);
        cudaFuncSetAttribute(k_mm<2,1>, cudaFuncAttributeMaxDynamicSharedMemorySize, MM_SM_END);
        cudaFuncSetAttribute(k_mm<2,2>, cudaFuncAttributeMaxDynamicSharedMemorySize, MM_SM_END);
        cudaFuncSetAttribute(k_mm<1,3>, cudaFuncAttributeMaxDynamicSharedMemorySize, MM_SM_END);
        attr_set = true;
    }

    const int T = 256;

    // degrees + norm
    k_deg_init<<<(NN + T - 1) / T, T>>>(pdeg);
    k_deg_edges<<<(EE + T - 1) / T, T>>>(col, pdeg);
    k_dinv<<<(NN + T - 1) / T, T>>>(pdeg, pdinv);

    // conversions / splits
    {
        size_t n8 = (size_t)EE * FE / 8;
        k_tof16_v<<<(int)((n8 + T - 1) / T), T>>>((const float4*)ea, (uint4*)pea16, n8);
    }
    k_w1t16<<<(HH * KTOT + T - 1) / T, T>>>(We1, pw1h);
    k_splitA<<<(int)(((size_t)NN * FN + T - 1) / T), T>>>(x, pxh, pxl, (size_t)NN * FN);
    k_splitWt<<<(128 * 64 + T - 1) / T, T>>>(We, wWeH, wWeL, 64, 128);
    k_splitWt<<<(128 * 128 + T - 1) / T, T>>>(Wc1, wC1H, wC1L, 128, 128);
    k_splitWt<<<(128 * 128 + T - 1) / T, T>>>(Wc2, wC2H, wC2L, 128, 128);
    k_splitWt<<<(128 * 128 + T - 1) / T, T>>>(Wn1, wN1H, wN1L, 128, 64);
    k_splitWt<<<(128 * 64 + T - 1) / T, T>>>(Wn2, wN2H, wN2L, 64, CN);

    // embed: h = relu(x @ We + be)  -> hh/hl
    k_mm<1,0><<<GRID_P, 512, MM_SM_END>>>(pxh, pxl, wWeH, wWeL, be, nullptr,
                                          nullptr, nullptr, phh, phl, NN, 128);
    // conv1 GEMM -> xw + selfloop acc
    k_mm<2,1><<<GRID_P, 512, MM_SM_END>>>(phh, phl, wC1H, wC1L, nullptr, pdinv,
                                          pxw, pacc, nullptr, nullptr, NN, 128);
    k_scatter<<<(int)(((size_t)EE * 32 + T - 1) / T), T>>>(pxw, row, col, pdinv, pacc);
    k_bias_relu_split<<<(int)(((size_t)NN * HH + T - 1) / T), T>>>(pacc, bc1, phh, phl);

    // conv2
    k_mm<2,1><<<GRID_P, 512, MM_SM_END>>>(phh, phl, wC2H, wC2L, nullptr, pdinv,
                                          pxw, pacc, nullptr, nullptr, NN, 128);
    k_scatter<<<(int)(((size_t)EE * 32 + T - 1) / T), T>>>(pxw, row, col, pdinv, pacc);
    k_bias_relu_split<<<(int)(((size_t)NN * HH + T - 1) / T), T>>>(pacc, bc2, phh, phl);

    // node head
    k_mm<2,2><<<GRID_P, 512, MM_SM_END>>>(phh, phl, wN1H, wN1L, bn1, nullptr,
                                          nullptr, nullptr, pth, ptl, NN, 64);
    k_mm<1,3><<<GRID_P, 512, MM_SM_END>>>(pth, ptl, wN2H, wN2L, bn2, nullptr,
                                          out_node, nullptr, nullptr, nullptr, NN, CN);

    // edge MLP (persistent, bulk-gather)
    k_edge<<<GRID_P, 512, ESM_END>>>(phh, pea16, pw1h, row, col,
                                     be1, We2, be2, out_edge);
}